// round 6
// baseline (speedup 1.0000x reference)
#include <cuda_runtime.h>
#include <cstdint>

#define DDIM 10
#define NPAIR 55
#define GTPB 256
#define GGRID 296            // 148 SMs x 2 blocks -> one full wave
#define ROWS_TILE 512        // rows per tile (2 rows / thread)
#define TILE_F4 (ROWS_TILE * DDIM / 4)   // 1280 float4 per tile
#define TILE_FLOATS (ROWS_TILE * DDIM)   // 5120 floats per tile
#define HID 16

// Deterministic two-stage reduction scratch (no atomics, no allocation).
__device__ float g_part[NPAIR][GGRID];

// ---------------------------------------------------------------------------
// async-copy helpers
// ---------------------------------------------------------------------------
__device__ __forceinline__ void cp_async16(uint32_t smem_dst, const void* gsrc) {
    asm volatile("cp.async.cg.shared.global [%0], [%1], 16;\n"
                 :: "r"(smem_dst), "l"(gsrc));
}
__device__ __forceinline__ void cp_commit() {
    asm volatile("cp.async.commit_group;\n");
}
__device__ __forceinline__ void cp_wait0() {
    asm volatile("cp.async.wait_group 0;\n");
}
__device__ __forceinline__ void cp_wait1() {
    asm volatile("cp.async.wait_group 1;\n");
}

// ---------------------------------------------------------------------------
// Kernel 1: Gram partials. Double-buffered cp.async staging (coalesced
// LDGSTS.128) overlapping next-tile loads with current-tile FMA.
// ---------------------------------------------------------------------------
__global__ void __launch_bounds__(GTPB, 2)
gram_kernel(const float* __restrict__ x, long long nrows) {
    __shared__ __align__(16) float sbuf[2][TILE_FLOATS];
    __shared__ float swarp[GTPB / 32][NPAIR];

    float acc[NPAIR];
#pragma unroll
    for (int k = 0; k < NPAIR; k++) acc[k] = 0.f;

    const long long ntiles = (nrows + ROWS_TILE - 1) / ROWS_TILE;
    const long long totalf4 = nrows * (long long)DDIM / 4;
    const float4* xsrc = reinterpret_cast<const float4*>(x);
    const uint32_t sbase = (uint32_t)__cvta_generic_to_shared(&sbuf[0][0]);

    long long t = blockIdx.x;
    bool havecur = (t < ntiles);

    // prologue: stage tile t into buffer 0
    if (havecur) {
        long long base4 = t * (long long)TILE_F4;
#pragma unroll
        for (int j = 0; j < TILE_F4 / GTPB; j++) {
            int i = threadIdx.x + j * GTPB;
            long long g4 = base4 + i;
            if (g4 < totalf4) {
                cp_async16(sbase + (uint32_t)i * 16u, xsrc + g4);
            } else {
                float4 z = make_float4(0.f, 0.f, 0.f, 0.f);
                reinterpret_cast<float4*>(&sbuf[0][0])[i] = z;
            }
        }
        cp_commit();
    }

    int buf = 0;
    while (havecur) {
        long long tn = t + (long long)GGRID;
        bool havenext = (tn < ntiles);
        if (havenext) {
            long long base4 = tn * (long long)TILE_F4;
            uint32_t dbase = sbase + (uint32_t)(buf ^ 1) * (TILE_FLOATS * 4u);
#pragma unroll
            for (int j = 0; j < TILE_F4 / GTPB; j++) {
                int i = threadIdx.x + j * GTPB;
                long long g4 = base4 + i;
                if (g4 < totalf4) {
                    cp_async16(dbase + (uint32_t)i * 16u, xsrc + g4);
                } else {
                    float4 z = make_float4(0.f, 0.f, 0.f, 0.f);
                    reinterpret_cast<float4*>(&sbuf[buf ^ 1][0])[i] = z;
                }
            }
            cp_commit();
            cp_wait1();          // current tile's group done
        } else {
            cp_wait0();
        }
        __syncthreads();

        // compute: this thread owns rows tid and tid+256 of the tile
        const float* sb = &sbuf[buf][0];
#pragma unroll
        for (int half = 0; half < 2; half++) {
            int r0 = threadIdx.x + half * GTPB;
            long long row_g = t * (long long)ROWS_TILE + r0;
            if (row_g < nrows) {
                float r[DDIM];
                const float2* rp = reinterpret_cast<const float2*>(sb + r0 * DDIM);
#pragma unroll
                for (int j = 0; j < 5; j++) {
                    float2 v = rp[j];
                    r[2 * j] = v.x;
                    r[2 * j + 1] = v.y;
                }
                int k = 0;
#pragma unroll
                for (int i = 0; i < DDIM; i++)
#pragma unroll
                    for (int j = i; j < DDIM; j++) acc[k++] += r[i] * r[j];
            }
        }
        __syncthreads();         // compute done before buf gets overwritten

        t = tn;
        havecur = havenext;
        buf ^= 1;
    }

    // warp reduce each accumulator
#pragma unroll
    for (int k = 0; k < NPAIR; k++) {
#pragma unroll
        for (int off = 16; off > 0; off >>= 1)
            acc[k] += __shfl_down_sync(0xffffffffu, acc[k], off);
    }
    int wid = threadIdx.x >> 5, lane = threadIdx.x & 31;
    if (lane == 0) {
#pragma unroll
        for (int k = 0; k < NPAIR; k++) swarp[wid][k] = acc[k];
    }
    __syncthreads();
    if (threadIdx.x < NPAIR) {
        float s = 0.f;
#pragma unroll
        for (int w = 0; w < GTPB / 32; w++) s += swarp[w][threadIdx.x];
        g_part[threadIdx.x][blockIdx.x] = s;
    }
}

// ---------------------------------------------------------------------------
// Fast-approx scalar helpers (sign-safe; ~1e-7 rel err, budget is 1e-3)
// ---------------------------------------------------------------------------
__device__ __forceinline__ float fdivf(float a, float b) { return __fdividef(a, b); }
__device__ __forceinline__ float fsqrta(float x) {
    float r;
    asm("sqrt.approx.f32 %0, %1;" : "=f"(r) : "f"(x));
    return r;   // sqrt.approx(+0) = +0
}

// ---------------------------------------------------------------------------
// LAPACK-faithful helpers (sign conventions preserved; magnitudes approx)
// ---------------------------------------------------------------------------
__device__ __forceinline__ float lapy2f(float x, float y) {
    float ax = fabsf(x), ay = fabsf(y);
    float w = fmaxf(ax, ay), z = fminf(ax, ay);
    if (z == 0.f) return w;
    float t = fdivf(z, w);
    return w * fsqrta(1.f + t * t);
}
__device__ __forceinline__ float signf(float a, float b) {
    return (b >= 0.f) ? fabsf(a) : -fabsf(a);
}
// LAPACK >= 3.10 slartg convention (c >= 0 always, r = sign(d, f))
__device__ __forceinline__ void lartgf(float f, float g, float& c, float& s, float& r) {
    if (g == 0.f) { c = 1.f; s = 0.f; r = f; }
    else if (f == 0.f) { c = 0.f; s = (g > 0.f) ? 1.f : -1.f; r = fabsf(g); }
    else {
        float d = fsqrta(f * f + g * g);
        c = fdivf(fabsf(f), d);
        r = signf(d, f);
        s = fdivf(g, r);
    }
}
// LAPACK slaev2 (2x2 symmetric eigenproblem with its exact sign logic)
__device__ void laev2f(float a, float b, float c_, float& rt1, float& rt2,
                       float& cs1, float& sn1) {
    float sm = a + c_;
    float df = a - c_;
    float adf = fabsf(df);
    float tb = b + b;
    float ab = fabsf(tb);
    float acmx, acmn;
    if (fabsf(a) > fabsf(c_)) { acmx = a; acmn = c_; } else { acmx = c_; acmn = a; }
    float rt;
    if (adf > ab)      { float q = fdivf(ab, adf); rt = adf * fsqrta(1.f + q * q); }
    else if (adf < ab) { float q = fdivf(adf, ab); rt = ab * fsqrta(1.f + q * q); }
    else               { rt = ab * fsqrta(2.f); }
    int sgn1;
    if (sm < 0.f) {
        rt1 = 0.5f * (sm - rt); sgn1 = -1;
        rt2 = fdivf(acmx, rt1) * acmn - fdivf(b, rt1) * b;
    } else if (sm > 0.f) {
        rt1 = 0.5f * (sm + rt); sgn1 = 1;
        rt2 = fdivf(acmx, rt1) * acmn - fdivf(b, rt1) * b;
    } else {
        rt1 = 0.5f * rt; rt2 = -0.5f * rt; sgn1 = 1;
    }
    float cs; int sgn2;
    if (df >= 0.f) { cs = df + rt; sgn2 = 1; }
    else           { cs = df - rt; sgn2 = -1; }
    float acs = fabsf(cs);
    if (acs > ab) {
        float ct = -fdivf(tb, cs);
        sn1 = rsqrtf(1.f + ct * ct);
        cs1 = ct * sn1;
    } else {
        if (ab == 0.f) { cs1 = 1.f; sn1 = 0.f; }
        else {
            float tn = -fdivf(cs, tb);
            cs1 = rsqrtf(1.f + tn * tn);
            sn1 = tn * cs1;
        }
    }
    if (sgn1 == sgn2) { float tn = cs1; cs1 = -sn1; sn1 = tn; }
}

// ---------------------------------------------------------------------------
// Kernel 2: partial-reduce (8 warps) then warp-parallel ssytd2 + ssteqr +
// sormtr + MLP on warp 0. Lanes redundantly run the scalar LAPACK chain
// (identical arithmetic -> identical signs); O(n) loops lane-distributed.
// ---------------------------------------------------------------------------
__global__ void solve_kernel(const float* __restrict__ W1, const float* __restrict__ b1,
                             const float* __restrict__ W2, const float* __restrict__ b2,
                             float* __restrict__ out) {
    __shared__ float gram[NPAIR];
    __shared__ float Am[DDIM][DDIM];
    __shared__ float Zm[DDIM][DDIM];
    __shared__ float dd[DDIM], ee[DDIM], tauv[DDIM], wcs[DDIM], wss[DDIM], pv[DDIM];

    const int tid = threadIdx.x;
    const int wrp = tid >> 5;
    const int lane = tid & 31;
    const int n = DDIM;

    // ---- stage 1: tree-reduce partials (all 8 warps) ----
    for (int k = wrp; k < NPAIR; k += 8) {
        float s = 0.f;
        for (int i = lane; i < GGRID; i += 32) s += g_part[k][i];
#pragma unroll
        for (int off = 16; off > 0; off >>= 1)
            s += __shfl_down_sync(0xffffffffu, s, off);
        if (lane == 0) gram[k] = s;
    }
    __syncthreads();
    if (tid >= 32) return;

    // scatter gram into full symmetric Am
    for (int k = lane; k < NPAIR; k += 32) {
        int i = 0, rem = k;
        while (rem >= n - i) { rem -= (n - i); i++; }
        int j = i + rem;
        float v = gram[k];
        Am[i][j] = v;
        Am[j][i] = v;
    }
    __syncwarp();

    // ---------------- ssytd2 (uplo='L') ----------------
    for (int i = 0; i < n - 1; i++) {
        float alpha = Am[i + 1][i];
        float xnorm = 0.f;
        for (int r = i + 2; r < n; r++) xnorm += Am[r][i] * Am[r][i];
        xnorm = fsqrta(xnorm);
        float taui = 0.f;
        if (xnorm != 0.f) {
            float beta = -signf(lapy2f(alpha, xnorm), alpha);
            taui = fdivf(beta - alpha, beta);
            float sc = fdivf(1.f, alpha - beta);
            if (lane >= i + 2 && lane < n) Am[lane][i] *= sc;
            if (lane == 0) Am[i + 1][i] = beta;
            __syncwarp();
        }
        ee[i] = Am[i + 1][i];
        if (taui != 0.f) {
            // pv[r] = taui * (A v)_r  (v[i+1]=1, v[r]=Am[r][i])
            if (lane >= i + 1 && lane < n) {
                int r = lane;
                float s = Am[r][i + 1];
                for (int c = i + 2; c < n; c++) s += Am[r][c] * Am[c][i];
                pv[r] = taui * s;
            }
            __syncwarp();
            float vtp = pv[i + 1];
            for (int r = i + 2; r < n; r++) vtp += pv[r] * Am[r][i];
            float alph = -0.5f * taui * vtp;
            __syncwarp();
            if (lane >= i + 1 && lane < n) {
                if (lane == i + 1) pv[lane] += alph;
                else               pv[lane] += alph * Am[lane][i];
            }
            __syncwarp();
            if (lane >= i + 1 && lane < n) {
                int r = lane;
                float vr = (r == i + 1) ? 1.f : Am[r][i];
                float wr = pv[r];
                for (int c = i + 1; c < n; c++) {
                    float vc = (c == i + 1) ? 1.f : Am[c][i];
                    Am[r][c] -= vr * pv[c] + wr * vc;
                }
            }
            __syncwarp();
        }
        dd[i] = Am[i][i];
        tauv[i] = taui;
        __syncwarp();
    }
    dd[n - 1] = Am[n - 1][n - 1];

    // Z = I (row-owned)
    if (lane < n)
        for (int c = 0; c < n; c++) Zm[lane][c] = (lane == c) ? 1.f : 0.f;
    __syncwarp();

    // ---------------- ssteqr (compz='I'); Zm row-owned ----------------
    {
        const float eps = 5.9604645e-8f;
        const float eps2 = eps * eps;
        const float safmin = 1.17549435e-38f;
        const int nmaxit = n * 30;
        int jtot = 0;
        int l1 = 1;
#define Dv(i) dd[(i) - 1]
#define Ev(i) ee[(i) - 1]
        while (l1 <= n) {
            if (l1 > 1) Ev(l1 - 1) = 0.f;
            int m = n;
            if (l1 <= n - 1) {
                for (int mm = l1; mm <= n - 1; mm++) {
                    float tst = fabsf(Ev(mm));
                    if (tst == 0.f) { m = mm; break; }
                    if (tst <= fsqrta(fabsf(Dv(mm))) * fsqrta(fabsf(Dv(mm + 1))) * eps) {
                        Ev(mm) = 0.f; m = mm; break;
                    }
                }
            }
            int l = l1, lend = m;
            l1 = m + 1;
            if (lend == l) continue;
            float anorm = 0.f;
            for (int i = l; i <= lend; i++) anorm = fmaxf(anorm, fabsf(Dv(i)));
            for (int i = l; i <= lend - 1; i++) anorm = fmaxf(anorm, fabsf(Ev(i)));
            if (anorm == 0.f) continue;
            if (fabsf(Dv(lend)) < fabsf(Dv(l))) { int t = l; l = lend; lend = t; }

            if (lend > l) {
                // ---- QL iteration ----
                while (true) {
                    int m2 = lend;
                    if (l != lend) {
                        for (int mm = l; mm <= lend - 1; mm++) {
                            float tst = fabsf(Ev(mm)); tst = tst * tst;
                            if (tst <= (eps2 * fabsf(Dv(mm))) * fabsf(Dv(mm + 1)) + safmin) { m2 = mm; break; }
                        }
                    }
                    if (m2 < lend) Ev(m2) = 0.f;
                    float p = Dv(l);
                    if (m2 == l) {
                        Dv(l) = p; l++;
                        if (l <= lend) continue;
                        break;
                    }
                    if (m2 == l + 1) {
                        float rt1, rt2, cc, ss;
                        laev2f(Dv(l), Ev(l), Dv(l + 1), rt1, rt2, cc, ss);
                        if (lane < n) {
                            float t1 = Zm[lane][l];
                            float t0 = Zm[lane][l - 1];
                            Zm[lane][l] = cc * t1 - ss * t0;
                            Zm[lane][l - 1] = ss * t1 + cc * t0;
                        }
                        Dv(l) = rt1; Dv(l + 1) = rt2; Ev(l) = 0.f;
                        l += 2;
                        if (l <= lend) continue;
                        break;
                    }
                    if (jtot == nmaxit) break;
                    jtot++;
                    float g = fdivf(Dv(l + 1) - p, 2.f * Ev(l));
                    float r = lapy2f(g, 1.f);
                    g = Dv(m2) - p + fdivf(Ev(l), g + signf(r, g));
                    float s = 1.f, c = 1.f; p = 0.f;
                    for (int i = m2 - 1; i >= l; i--) {
                        float f = s * Ev(i), b = c * Ev(i);
                        lartgf(g, f, c, s, r);
                        if (i != m2 - 1) Ev(i + 1) = r;
                        g = Dv(i + 1) - p;
                        r = (Dv(i) - g) * s + 2.f * c * b;
                        p = s * r;
                        Dv(i + 1) = g + p;
                        g = c * r - b;
                        wcs[i - 1] = c;
                        wss[i - 1] = -s;                 // LAPACK stores -s for QL
                    }
                    if (lane < n) {
                        for (int j = m2 - l; j >= 1; j--) {
                            float ct = wcs[(l - 1) + (j - 1)], st = wss[(l - 1) + (j - 1)];
                            if (ct != 1.f || st != 0.f) {
                                int c1 = (l - 1) + j, c0 = c1 - 1;
                                float temp = Zm[lane][c1];
                                Zm[lane][c1] = ct * temp - st * Zm[lane][c0];
                                Zm[lane][c0] = st * temp + ct * Zm[lane][c0];
                            }
                        }
                    }
                    Dv(l) -= p;
                    Ev(l) = g;
                }
            } else {
                // ---- QR iteration ----
                while (true) {
                    int m2 = lend;
                    if (l != lend) {
                        for (int mm = l; mm >= lend + 1; mm--) {
                            float tst = fabsf(Ev(mm - 1)); tst = tst * tst;
                            if (tst <= (eps2 * fabsf(Dv(mm))) * fabsf(Dv(mm - 1)) + safmin) { m2 = mm; break; }
                        }
                    }
                    if (m2 > lend) Ev(m2 - 1) = 0.f;
                    float p = Dv(l);
                    if (m2 == l) {
                        Dv(l) = p; l--;
                        if (l >= lend) continue;
                        break;
                    }
                    if (m2 == l - 1) {
                        float rt1, rt2, cc, ss;
                        laev2f(Dv(l - 1), Ev(l - 1), Dv(l), rt1, rt2, cc, ss);
                        if (lane < n) {
                            float t1 = Zm[lane][l - 1];
                            float t0 = Zm[lane][l - 2];
                            Zm[lane][l - 1] = cc * t1 - ss * t0;
                            Zm[lane][l - 2] = ss * t1 + cc * t0;
                        }
                        Dv(l - 1) = rt1; Dv(l) = rt2; Ev(l - 1) = 0.f;
                        l -= 2;
                        if (l >= lend) continue;
                        break;
                    }
                    if (jtot == nmaxit) break;
                    jtot++;
                    float g = fdivf(Dv(l - 1) - p, 2.f * Ev(l - 1));
                    float r = lapy2f(g, 1.f);
                    g = Dv(m2) - p + fdivf(Ev(l - 1), g + signf(r, g));
                    float s = 1.f, c = 1.f; p = 0.f;
                    for (int i = m2; i <= l - 1; i++) {
                        float f = s * Ev(i), b = c * Ev(i);
                        lartgf(g, f, c, s, r);
                        if (i != m2) Ev(i - 1) = r;
                        g = Dv(i) - p;
                        r = (Dv(i + 1) - g) * s + 2.f * c * b;
                        p = s * r;
                        Dv(i) = g + p;
                        g = c * r - b;
                        wcs[i - 1] = c;
                        wss[i - 1] = s;
                    }
                    if (lane < n) {
                        for (int j = 1; j <= l - m2; j++) {
                            float ct = wcs[(m2 - 1) + (j - 1)], st = wss[(m2 - 1) + (j - 1)];
                            if (ct != 1.f || st != 0.f) {
                                int c1 = (m2 - 1) + j, c0 = c1 - 1;
                                float temp = Zm[lane][c1];
                                Zm[lane][c1] = ct * temp - st * Zm[lane][c0];
                                Zm[lane][c0] = st * temp + ct * Zm[lane][c0];
                            }
                        }
                    }
                    Dv(l) -= p;
                    Ev(l - 1) = g;
                }
            }
        }
        // selection sort ascending + column swaps (lane owns row)
        for (int ii = 2; ii <= n; ii++) {
            int i = ii - 1, k = i;
            float p = Dv(i);
            for (int j = ii; j <= n; j++)
                if (Dv(j) < p) { k = j; p = Dv(j); }
            if (k != i) {
                Dv(k) = Dv(i); Dv(i) = p;
                if (lane < n) {
                    float t = Zm[lane][i - 1];
                    Zm[lane][i - 1] = Zm[lane][k - 1];
                    Zm[lane][k - 1] = t;
                }
            }
        }
#undef Dv
#undef Ev
    }
    __syncwarp();   // Zm switches row-owned -> column-owned

    // ---------------- sormtr: Z := H(1)...H(n-1) Z ; lane owns column ----
    for (int i = n - 2; i >= 0; i--) {
        if (tauv[i] == 0.f) continue;
        if (lane < n) {
            int c = lane;
            float s = Zm[i + 1][c];
            for (int r = i + 2; r < n; r++) s += Am[r][i] * Zm[r][c];
            s *= tauv[i];
            Zm[i + 1][c] -= s;
            for (int r = i + 2; r < n; r++) Zm[r][c] -= s * Am[r][i];
        }
    }
    __syncwarp();   // back to row reads for the MLP

    // ---------------- MLP: relu(w @ W1^T + b1) @ W2^T + b2; 0.5*(sigmoid+1)
    if (lane < n) {
        float zr[DDIM];
#pragma unroll
        for (int k = 0; k < DDIM; k++) zr[k] = Zm[lane][k];
        float y2 = b2[0];
        for (int h = 0; h < HID; h++) {
            float a = b1[h];
#pragma unroll
            for (int k = 0; k < DDIM; k++) a += zr[k] * W1[h * DDIM + k];
            a = fmaxf(a, 0.f);
            y2 += a * W2[h];
        }
        out[lane] = 0.5f * (fdivf(1.f, 1.f + __expf(-y2)) + 1.f);
    }
}

// ---------------------------------------------------------------------------
extern "C" void kernel_launch(void* const* d_in, const int* in_sizes, int n_in,
                              void* d_out, int out_size) {
    const float* x  = (const float*)d_in[0];
    const float* W1 = (const float*)d_in[1];
    const float* b1 = (const float*)d_in[2];
    const float* W2 = (const float*)d_in[3];
    const float* b2 = (const float*)d_in[4];
    long long nrows = (long long)in_sizes[0] / DDIM;

    gram_kernel<<<GGRID, GTPB>>>(x, nrows);
    solve_kernel<<<1, GTPB>>>(W1, b1, W2, b2, (float*)d_out);
}

// round 7
// speedup vs baseline: 1.0725x; 1.0725x over previous
#include <cuda_runtime.h>
#include <cstdint>

#define DDIM 10
#define NPAIR 55
#define GTPB 256
#define GGRID 296            // 148 SMs x 2 blocks -> one full wave
#define ROWS_TILE 512        // rows per tile (2 rows / thread)
#define TILE_F4 (ROWS_TILE * DDIM / 4)   // 1280 float4 per tile
#define TILE_FLOATS (ROWS_TILE * DDIM)   // 5120 floats per tile
#define HID 16

// Deterministic two-stage reduction scratch (no atomics, no allocation).
__device__ float g_part[NPAIR][GGRID];

// ---------------------------------------------------------------------------
// async-copy helpers
// ---------------------------------------------------------------------------
__device__ __forceinline__ void cp_async16(uint32_t smem_dst, const void* gsrc) {
    asm volatile("cp.async.cg.shared.global [%0], [%1], 16;\n"
                 :: "r"(smem_dst), "l"(gsrc));
}
__device__ __forceinline__ void cp_commit() {
    asm volatile("cp.async.commit_group;\n");
}
__device__ __forceinline__ void cp_wait0() {
    asm volatile("cp.async.wait_group 0;\n");
}
__device__ __forceinline__ void cp_wait1() {
    asm volatile("cp.async.wait_group 1;\n");
}

// ---------------------------------------------------------------------------
// Kernel 1: Gram partials. Double-buffered cp.async staging (coalesced
// LDGSTS.128) overlapping next-tile loads with current-tile FMA. (Unchanged
// from the passing 28us version.)
// ---------------------------------------------------------------------------
__global__ void __launch_bounds__(GTPB, 2)
gram_kernel(const float* __restrict__ x, long long nrows) {
    __shared__ __align__(16) float sbuf[2][TILE_FLOATS];
    __shared__ float swarp[GTPB / 32][NPAIR];

    float acc[NPAIR];
#pragma unroll
    for (int k = 0; k < NPAIR; k++) acc[k] = 0.f;

    const long long ntiles = (nrows + ROWS_TILE - 1) / ROWS_TILE;
    const long long totalf4 = nrows * (long long)DDIM / 4;
    const float4* xsrc = reinterpret_cast<const float4*>(x);
    const uint32_t sbase = (uint32_t)__cvta_generic_to_shared(&sbuf[0][0]);

    long long t = blockIdx.x;
    bool havecur = (t < ntiles);

    if (havecur) {
        long long base4 = t * (long long)TILE_F4;
#pragma unroll
        for (int j = 0; j < TILE_F4 / GTPB; j++) {
            int i = threadIdx.x + j * GTPB;
            long long g4 = base4 + i;
            if (g4 < totalf4) {
                cp_async16(sbase + (uint32_t)i * 16u, xsrc + g4);
            } else {
                float4 z = make_float4(0.f, 0.f, 0.f, 0.f);
                reinterpret_cast<float4*>(&sbuf[0][0])[i] = z;
            }
        }
        cp_commit();
    }

    int buf = 0;
    while (havecur) {
        long long tn = t + (long long)GGRID;
        bool havenext = (tn < ntiles);
        if (havenext) {
            long long base4 = tn * (long long)TILE_F4;
            uint32_t dbase = sbase + (uint32_t)(buf ^ 1) * (TILE_FLOATS * 4u);
#pragma unroll
            for (int j = 0; j < TILE_F4 / GTPB; j++) {
                int i = threadIdx.x + j * GTPB;
                long long g4 = base4 + i;
                if (g4 < totalf4) {
                    cp_async16(dbase + (uint32_t)i * 16u, xsrc + g4);
                } else {
                    float4 z = make_float4(0.f, 0.f, 0.f, 0.f);
                    reinterpret_cast<float4*>(&sbuf[buf ^ 1][0])[i] = z;
                }
            }
            cp_commit();
            cp_wait1();
        } else {
            cp_wait0();
        }
        __syncthreads();

        const float* sb = &sbuf[buf][0];
#pragma unroll
        for (int half = 0; half < 2; half++) {
            int r0 = threadIdx.x + half * GTPB;
            long long row_g = t * (long long)ROWS_TILE + r0;
            if (row_g < nrows) {
                float r[DDIM];
                const float2* rp = reinterpret_cast<const float2*>(sb + r0 * DDIM);
#pragma unroll
                for (int j = 0; j < 5; j++) {
                    float2 v = rp[j];
                    r[2 * j] = v.x;
                    r[2 * j + 1] = v.y;
                }
                int k = 0;
#pragma unroll
                for (int i = 0; i < DDIM; i++)
#pragma unroll
                    for (int j = i; j < DDIM; j++) acc[k++] += r[i] * r[j];
            }
        }
        __syncthreads();

        t = tn;
        havecur = havenext;
        buf ^= 1;
    }

#pragma unroll
    for (int k = 0; k < NPAIR; k++) {
#pragma unroll
        for (int off = 16; off > 0; off >>= 1)
            acc[k] += __shfl_down_sync(0xffffffffu, acc[k], off);
    }
    int wid = threadIdx.x >> 5, lane = threadIdx.x & 31;
    if (lane == 0) {
#pragma unroll
        for (int k = 0; k < NPAIR; k++) swarp[wid][k] = acc[k];
    }
    __syncthreads();
    if (threadIdx.x < NPAIR) {
        float s = 0.f;
#pragma unroll
        for (int w = 0; w < GTPB / 32; w++) s += swarp[w][threadIdx.x];
        g_part[threadIdx.x][blockIdx.x] = s;
    }
}

// ---------------------------------------------------------------------------
// Fast-approx scalar helpers (sign-safe; ~1e-7 rel err, budget is 1e-3)
// ---------------------------------------------------------------------------
__device__ __forceinline__ float fdivf(float a, float b) { return __fdividef(a, b); }
__device__ __forceinline__ float fsqrta(float x) {
    float r;
    asm("sqrt.approx.f32 %0, %1;" : "=f"(r) : "f"(x));
    return r;
}

// register-array dynamic-index helpers (compile to SEL chains; arrays stay
// in registers because every access is compile-time-indexed after unroll)
__device__ __forceinline__ float rget(const float a[DDIM], int i) {
    float v = a[0];
#pragma unroll
    for (int k = 1; k < DDIM; k++) if (k == i) v = a[k];
    return v;
}
__device__ __forceinline__ void rset(float a[DDIM], int i, float v) {
#pragma unroll
    for (int k = 0; k < DDIM; k++) if (k == i) a[k] = v;
}
// rotate register-Z columns (c0, c1) with LAPACK slasr element formula
__device__ __forceinline__ void zrot(float Z[DDIM], int c0, int c1, float cc, float ss) {
    float t1 = rget(Z, c1), t0 = rget(Z, c0);
    rset(Z, c1, cc * t1 - ss * t0);
    rset(Z, c0, ss * t1 + cc * t0);
}

// ---------------------------------------------------------------------------
// LAPACK-faithful helpers (sign conventions preserved; magnitudes approx)
// ---------------------------------------------------------------------------
__device__ __forceinline__ float lapy2f(float x, float y) {
    float ax = fabsf(x), ay = fabsf(y);
    float w = fmaxf(ax, ay), z = fminf(ax, ay);
    if (z == 0.f) return w;
    float t = fdivf(z, w);
    return w * fsqrta(1.f + t * t);
}
__device__ __forceinline__ float signf(float a, float b) {
    return (b >= 0.f) ? fabsf(a) : -fabsf(a);
}
// LAPACK >= 3.10 slartg convention (c >= 0 always, r = sign(d, f))
__device__ __forceinline__ void lartgf(float f, float g, float& c, float& s, float& r) {
    if (g == 0.f) { c = 1.f; s = 0.f; r = f; }
    else if (f == 0.f) { c = 0.f; s = (g > 0.f) ? 1.f : -1.f; r = fabsf(g); }
    else {
        float d = fsqrta(f * f + g * g);
        c = fdivf(fabsf(f), d);
        r = signf(d, f);
        s = fdivf(g, r);
    }
}
// LAPACK slaev2 (2x2 symmetric eigenproblem with its exact sign logic)
__device__ void laev2f(float a, float b, float c_, float& rt1, float& rt2,
                       float& cs1, float& sn1) {
    float sm = a + c_;
    float df = a - c_;
    float adf = fabsf(df);
    float tb = b + b;
    float ab = fabsf(tb);
    float acmx, acmn;
    if (fabsf(a) > fabsf(c_)) { acmx = a; acmn = c_; } else { acmx = c_; acmn = a; }
    float rt;
    if (adf > ab)      { float q = fdivf(ab, adf); rt = adf * fsqrta(1.f + q * q); }
    else if (adf < ab) { float q = fdivf(adf, ab); rt = ab * fsqrta(1.f + q * q); }
    else               { rt = ab * fsqrta(2.f); }
    int sgn1;
    if (sm < 0.f) {
        rt1 = 0.5f * (sm - rt); sgn1 = -1;
        rt2 = fdivf(acmx, rt1) * acmn - fdivf(b, rt1) * b;
    } else if (sm > 0.f) {
        rt1 = 0.5f * (sm + rt); sgn1 = 1;
        rt2 = fdivf(acmx, rt1) * acmn - fdivf(b, rt1) * b;
    } else {
        rt1 = 0.5f * rt; rt2 = -0.5f * rt; sgn1 = 1;
    }
    float cs; int sgn2;
    if (df >= 0.f) { cs = df + rt; sgn2 = 1; }
    else           { cs = df - rt; sgn2 = -1; }
    float acs = fabsf(cs);
    if (acs > ab) {
        float ct = -fdivf(tb, cs);
        sn1 = rsqrtf(1.f + ct * ct);
        cs1 = ct * sn1;
    } else {
        if (ab == 0.f) { cs1 = 1.f; sn1 = 0.f; }
        else {
            float tn = -fdivf(cs, tb);
            cs1 = rsqrtf(1.f + tn * tn);
            sn1 = tn * cs1;
        }
    }
    if (sgn1 == sgn2) { float tn = cs1; cs1 = -sn1; sn1 = tn; }
}

// ---------------------------------------------------------------------------
// Kernel 2: partial-reduce (8 warps), then warp-0 ssytd2 (smem) + steqr with
// REGISTER-resident D/E/Z (all lanes redundantly run the scalar LAPACK chain;
// each lane's registers hold its Z row; rotations applied inline in the exact
// LAPACK slasr order) + sormtr + MLP.
// ---------------------------------------------------------------------------
__global__ void solve_kernel(const float* __restrict__ W1, const float* __restrict__ b1,
                             const float* __restrict__ W2, const float* __restrict__ b2,
                             float* __restrict__ out) {
    __shared__ float gram[NPAIR];
    __shared__ float Am[DDIM][DDIM];
    __shared__ float Zm[DDIM][DDIM];
    __shared__ float dd[DDIM], ee[DDIM], tauv[DDIM], pv[DDIM];

    const int tid = threadIdx.x;
    const int wrp = tid >> 5;
    const int lane = tid & 31;
    const int n = DDIM;

    // ---- stage 1: tree-reduce partials (all 8 warps) ----
    for (int k = wrp; k < NPAIR; k += 8) {
        float s = 0.f;
        for (int i = lane; i < GGRID; i += 32) s += g_part[k][i];
#pragma unroll
        for (int off = 16; off > 0; off >>= 1)
            s += __shfl_down_sync(0xffffffffu, s, off);
        if (lane == 0) gram[k] = s;
    }
    __syncthreads();
    if (tid >= 32) return;

    // scatter gram into full symmetric Am
    for (int k = lane; k < NPAIR; k += 32) {
        int i = 0, rem = k;
        while (rem >= n - i) { rem -= (n - i); i++; }
        int j = i + rem;
        float v = gram[k];
        Am[i][j] = v;
        Am[j][i] = v;
    }
    __syncwarp();

    // ---------------- ssytd2 (uplo='L'), smem Am ----------------
    for (int i = 0; i < n - 1; i++) {
        float alpha = Am[i + 1][i];
        float xnorm = 0.f;
        for (int r = i + 2; r < n; r++) xnorm += Am[r][i] * Am[r][i];
        xnorm = fsqrta(xnorm);
        float taui = 0.f;
        if (xnorm != 0.f) {
            float beta = -signf(lapy2f(alpha, xnorm), alpha);
            taui = fdivf(beta - alpha, beta);
            float sc = fdivf(1.f, alpha - beta);
            if (lane >= i + 2 && lane < n) Am[lane][i] *= sc;
            if (lane == 0) Am[i + 1][i] = beta;
            __syncwarp();
        }
        ee[i] = Am[i + 1][i];
        if (taui != 0.f) {
            if (lane >= i + 1 && lane < n) {
                int r = lane;
                float s = Am[r][i + 1];
                for (int c = i + 2; c < n; c++) s += Am[r][c] * Am[c][i];
                pv[r] = taui * s;
            }
            __syncwarp();
            float vtp = pv[i + 1];
            for (int r = i + 2; r < n; r++) vtp += pv[r] * Am[r][i];
            float alph = -0.5f * taui * vtp;
            __syncwarp();
            if (lane >= i + 1 && lane < n) {
                if (lane == i + 1) pv[lane] += alph;
                else               pv[lane] += alph * Am[lane][i];
            }
            __syncwarp();
            if (lane >= i + 1 && lane < n) {
                int r = lane;
                float vr = (r == i + 1) ? 1.f : Am[r][i];
                float wr = pv[r];
                for (int c = i + 1; c < n; c++) {
                    float vc = (c == i + 1) ? 1.f : Am[c][i];
                    Am[r][c] -= vr * pv[c] + wr * vc;
                }
            }
            __syncwarp();
        }
        dd[i] = Am[i][i];
        tauv[i] = taui;
        __syncwarp();
    }
    dd[n - 1] = Am[n - 1][n - 1];
    __syncwarp();

    // ---- load D/E/Z into registers (replicated across lanes) ----
    float D[DDIM], E[DDIM], Z[DDIM];
#pragma unroll
    for (int k = 0; k < DDIM; k++) {
        D[k] = dd[k];
        E[k] = (k < DDIM - 1) ? ee[k] : 0.f;
        Z[k] = (lane == k) ? 1.f : 0.f;   // lane owns Z row 'lane'
    }

    // ---------------- ssteqr (compz='I'), fully register-resident ----------
    {
        const float eps = 5.9604645e-8f;
        const float eps2 = eps * eps;
        const float safmin = 1.17549435e-38f;
        const int nmaxit = n * 30;
        int jtot = 0;
        int l1 = 1;
        // 1-based LAPACK indices: Dv(i) = D[i-1], Ev(i) = E[i-1]
        while (l1 <= n) {
            if (l1 > 1) rset(E, l1 - 2, 0.f);
            int m = n;
            {
                bool found = false;
#pragma unroll
                for (int mm = 1; mm <= DDIM - 1; mm++) {
                    if (!found && mm >= l1) {
                        float tst = fabsf(E[mm - 1]);
                        if (tst == 0.f) { m = mm; found = true; }
                        else if (tst <= fsqrta(fabsf(D[mm - 1])) * fsqrta(fabsf(D[mm])) * eps) {
                            E[mm - 1] = 0.f; m = mm; found = true;
                        }
                    }
                }
            }
            int l = l1, lend = m;
            l1 = m + 1;
            if (lend == l) continue;
            float anorm = 0.f;
#pragma unroll
            for (int i = 1; i <= DDIM; i++)
                if (i >= l && i <= lend) anorm = fmaxf(anorm, fabsf(D[i - 1]));
#pragma unroll
            for (int i = 1; i <= DDIM - 1; i++)
                if (i >= l && i <= lend - 1) anorm = fmaxf(anorm, fabsf(E[i - 1]));
            if (anorm == 0.f) continue;
            if (fabsf(rget(D, lend - 1)) < fabsf(rget(D, l - 1))) { int t = l; l = lend; lend = t; }

            if (lend > l) {
                // ---- QL iteration ----
                while (true) {
                    int m2 = lend;
                    if (l != lend) {
                        bool found = false;
#pragma unroll
                        for (int mm = 1; mm <= DDIM - 1; mm++) {
                            if (!found && mm >= l && mm <= lend - 1) {
                                float tst = fabsf(E[mm - 1]); tst = tst * tst;
                                if (tst <= (eps2 * fabsf(D[mm - 1])) * fabsf(D[mm]) + safmin) {
                                    m2 = mm; found = true;
                                }
                            }
                        }
                    }
                    if (m2 < lend) rset(E, m2 - 1, 0.f);
                    float p = rget(D, l - 1);
                    if (m2 == l) {
                        l++;
                        if (l <= lend) continue;
                        break;
                    }
                    if (m2 == l + 1) {
                        float rt1, rt2, cc, ss;
                        laev2f(rget(D, l - 1), rget(E, l - 1), rget(D, l), rt1, rt2, cc, ss);
                        zrot(Z, l - 1, l, cc, ss);           // cols (l-1, l) 0-based
                        rset(D, l - 1, rt1); rset(D, l, rt2); rset(E, l - 1, 0.f);
                        l += 2;
                        if (l <= lend) continue;
                        break;
                    }
                    if (jtot == nmaxit) break;
                    jtot++;
                    float g = fdivf(rget(D, l) - p, 2.f * rget(E, l - 1));
                    float r = lapy2f(g, 1.f);
                    g = rget(D, m2 - 1) - p + fdivf(rget(E, l - 1), g + signf(r, g));
                    float s = 1.f, c = 1.f; p = 0.f;
                    // rotations generated i = m2-1 downto l; LAPACK slasr 'B'
                    // replays them in this same order -> apply inline.
#pragma unroll
                    for (int i = DDIM - 1; i >= 1; i--) {
                        if (i <= m2 - 1 && i >= l) {
                            float f = s * E[i - 1], b = c * E[i - 1];
                            float rr;
                            lartgf(g, f, c, s, rr);
                            if (i != m2 - 1) E[i] = rr;
                            g = D[i] - p;
                            float r2 = (D[i - 1] - g) * s + 2.f * c * b;
                            p = s * r2;
                            D[i] = g + p;
                            g = c * r2 - b;
                            // ct=c, st=-s applied to Z cols (i-1, i):
                            float t1 = Z[i], t0 = Z[i - 1];
                            Z[i]     = c * t1 + s * t0;      // ct*t1 - st*t0
                            Z[i - 1] = -s * t1 + c * t0;     // st*t1 + ct*t0
                        }
                    }
                    rset(D, l - 1, rget(D, l - 1) - p);
                    rset(E, l - 1, g);
                }
            } else {
                // ---- QR iteration ----
                while (true) {
                    int m2 = lend;
                    if (l != lend) {
                        bool found = false;
#pragma unroll
                        for (int mm = DDIM; mm >= 2; mm--) {
                            if (!found && mm <= l && mm >= lend + 1) {
                                float tst = fabsf(E[mm - 2]); tst = tst * tst;
                                if (tst <= (eps2 * fabsf(D[mm - 1])) * fabsf(D[mm - 2]) + safmin) {
                                    m2 = mm; found = true;
                                }
                            }
                        }
                    }
                    if (m2 > lend) rset(E, m2 - 2, 0.f);
                    float p = rget(D, l - 1);
                    if (m2 == l) {
                        l--;
                        if (l >= lend) continue;
                        break;
                    }
                    if (m2 == l - 1) {
                        float rt1, rt2, cc, ss;
                        laev2f(rget(D, l - 2), rget(E, l - 2), rget(D, l - 1), rt1, rt2, cc, ss);
                        zrot(Z, l - 2, l - 1, cc, ss);       // cols (l-2, l-1) 0-based
                        rset(D, l - 2, rt1); rset(D, l - 1, rt2); rset(E, l - 2, 0.f);
                        l -= 2;
                        if (l >= lend) continue;
                        break;
                    }
                    if (jtot == nmaxit) break;
                    jtot++;
                    float g = fdivf(rget(D, l - 2) - p, 2.f * rget(E, l - 2));
                    float r = lapy2f(g, 1.f);
                    g = rget(D, m2 - 1) - p + fdivf(rget(E, l - 2), g + signf(r, g));
                    float s = 1.f, c = 1.f; p = 0.f;
                    // rotations generated i = m2 .. l-1; slasr 'F' replays in
                    // the same ascending order -> apply inline.
#pragma unroll
                    for (int i = 1; i <= DDIM - 1; i++) {
                        if (i >= m2 && i <= l - 1) {
                            float f = s * E[i - 1], b = c * E[i - 1];
                            float rr;
                            lartgf(g, f, c, s, rr);
                            if (i >= 2 && i != m2) E[i - 2] = rr;
                            g = D[i - 1] - p;
                            float r2 = (D[i] - g) * s + 2.f * c * b;
                            p = s * r2;
                            D[i - 1] = g + p;
                            g = c * r2 - b;
                            // ct=c, st=s applied to Z cols (i-1, i):
                            float t1 = Z[i], t0 = Z[i - 1];
                            Z[i]     = c * t1 - s * t0;
                            Z[i - 1] = s * t1 + c * t0;
                        }
                    }
                    rset(D, l - 1, rget(D, l - 1) - p);
                    rset(E, l - 2, g);
                }
            }
        }

        // selection sort ascending + Z column swaps (register selects)
#pragma unroll
        for (int ii = 2; ii <= DDIM; ii++) {
            int k = ii - 1;
            float p = D[ii - 2];
#pragma unroll
            for (int j = 2; j <= DDIM; j++) {
                if (j >= ii) {
                    float dj = D[j - 1];
                    if (dj < p) { k = j; p = dj; }
                }
            }
            if (k != ii - 1) {
                rset(D, k - 1, D[ii - 2]);
                D[ii - 2] = p;
                float t = Z[ii - 2];
                Z[ii - 2] = rget(Z, k - 1);
                rset(Z, k - 1, t);
            }
        }
    }

    // dump register Z rows to smem for the column-owned sormtr pass
    if (lane < n) {
#pragma unroll
        for (int k = 0; k < DDIM; k++) Zm[lane][k] = Z[k];
    }
    __syncwarp();

    // ---------------- sormtr: Z := H(1)...H(n-1) Z ; lane owns column ----
    for (int i = n - 2; i >= 0; i--) {
        if (tauv[i] == 0.f) continue;
        if (lane < n) {
            int c = lane;
            float s = Zm[i + 1][c];
            for (int r = i + 2; r < n; r++) s += Am[r][i] * Zm[r][c];
            s *= tauv[i];
            Zm[i + 1][c] -= s;
            for (int r = i + 2; r < n; r++) Zm[r][c] -= s * Am[r][i];
        }
    }
    __syncwarp();   // back to row reads for the MLP

    // ---------------- MLP: relu(w @ W1^T + b1) @ W2^T + b2; 0.5*(sigmoid+1)
    if (lane < n) {
        float zr[DDIM];
#pragma unroll
        for (int k = 0; k < DDIM; k++) zr[k] = Zm[lane][k];
        float y2 = b2[0];
        for (int h = 0; h < HID; h++) {
            float a = b1[h];
#pragma unroll
            for (int k = 0; k < DDIM; k++) a += zr[k] * W1[h * DDIM + k];
            a = fmaxf(a, 0.f);
            y2 += a * W2[h];
        }
        out[lane] = 0.5f * (fdivf(1.f, 1.f + __expf(-y2)) + 1.f);
    }
}

// ---------------------------------------------------------------------------
extern "C" void kernel_launch(void* const* d_in, const int* in_sizes, int n_in,
                              void* d_out, int out_size) {
    const float* x  = (const float*)d_in[0];
    const float* W1 = (const float*)d_in[1];
    const float* b1 = (const float*)d_in[2];
    const float* W2 = (const float*)d_in[3];
    const float* b2 = (const float*)d_in[4];
    long long nrows = (long long)in_sizes[0] / DDIM;

    gram_kernel<<<GGRID, GTPB>>>(x, nrows);
    solve_kernel<<<1, GTPB>>>(W1, b1, W2, b2, (float*)d_out);
}

// round 8
// speedup vs baseline: 1.0844x; 1.0110x over previous
#include <cuda_runtime.h>
#include <cstdint>

#define DDIM 10
#define NPAIR 55
#define GTPB 256
#define GGRID 296            // 148 SMs x 2 blocks -> one full wave
#define ROWS_TILE 512        // rows per tile (2 rows / thread)
#define TILE_F4 (ROWS_TILE * DDIM / 4)   // 1280 float4 per tile
#define TILE_FLOATS (ROWS_TILE * DDIM)   // 5120 floats per tile
#define HID 16

// Deterministic two-stage reduction scratch (no atomics, no allocation).
__device__ float g_part[NPAIR][GGRID];

// ---------------------------------------------------------------------------
// async-copy helpers
// ---------------------------------------------------------------------------
__device__ __forceinline__ void cp_async16(uint32_t smem_dst, const void* gsrc) {
    asm volatile("cp.async.cg.shared.global [%0], [%1], 16;\n"
                 :: "r"(smem_dst), "l"(gsrc));
}
__device__ __forceinline__ void cp_commit() {
    asm volatile("cp.async.commit_group;\n");
}
__device__ __forceinline__ void cp_wait0() {
    asm volatile("cp.async.wait_group 0;\n");
}
__device__ __forceinline__ void cp_wait1() {
    asm volatile("cp.async.wait_group 1;\n");
}

// ---------------------------------------------------------------------------
// Kernel 1: Gram partials. Double-buffered cp.async staging (coalesced
// LDGSTS.128) overlapping next-tile loads with current-tile FMA. (Unchanged
// from the passing 28us version.)
// ---------------------------------------------------------------------------
__global__ void __launch_bounds__(GTPB, 2)
gram_kernel(const float* __restrict__ x, long long nrows) {
    __shared__ __align__(16) float sbuf[2][TILE_FLOATS];
    __shared__ float swarp[GTPB / 32][NPAIR];

    float acc[NPAIR];
#pragma unroll
    for (int k = 0; k < NPAIR; k++) acc[k] = 0.f;

    const long long ntiles = (nrows + ROWS_TILE - 1) / ROWS_TILE;
    const long long totalf4 = nrows * (long long)DDIM / 4;
    const float4* xsrc = reinterpret_cast<const float4*>(x);
    const uint32_t sbase = (uint32_t)__cvta_generic_to_shared(&sbuf[0][0]);

    long long t = blockIdx.x;
    bool havecur = (t < ntiles);

    if (havecur) {
        long long base4 = t * (long long)TILE_F4;
#pragma unroll
        for (int j = 0; j < TILE_F4 / GTPB; j++) {
            int i = threadIdx.x + j * GTPB;
            long long g4 = base4 + i;
            if (g4 < totalf4) {
                cp_async16(sbase + (uint32_t)i * 16u, xsrc + g4);
            } else {
                float4 z = make_float4(0.f, 0.f, 0.f, 0.f);
                reinterpret_cast<float4*>(&sbuf[0][0])[i] = z;
            }
        }
        cp_commit();
    }

    int buf = 0;
    while (havecur) {
        long long tn = t + (long long)GGRID;
        bool havenext = (tn < ntiles);
        if (havenext) {
            long long base4 = tn * (long long)TILE_F4;
            uint32_t dbase = sbase + (uint32_t)(buf ^ 1) * (TILE_FLOATS * 4u);
#pragma unroll
            for (int j = 0; j < TILE_F4 / GTPB; j++) {
                int i = threadIdx.x + j * GTPB;
                long long g4 = base4 + i;
                if (g4 < totalf4) {
                    cp_async16(dbase + (uint32_t)i * 16u, xsrc + g4);
                } else {
                    float4 z = make_float4(0.f, 0.f, 0.f, 0.f);
                    reinterpret_cast<float4*>(&sbuf[buf ^ 1][0])[i] = z;
                }
            }
            cp_commit();
            cp_wait1();
        } else {
            cp_wait0();
        }
        __syncthreads();

        const float* sb = &sbuf[buf][0];
#pragma unroll
        for (int half = 0; half < 2; half++) {
            int r0 = threadIdx.x + half * GTPB;
            long long row_g = t * (long long)ROWS_TILE + r0;
            if (row_g < nrows) {
                float r[DDIM];
                const float2* rp = reinterpret_cast<const float2*>(sb + r0 * DDIM);
#pragma unroll
                for (int j = 0; j < 5; j++) {
                    float2 v = rp[j];
                    r[2 * j] = v.x;
                    r[2 * j + 1] = v.y;
                }
                int k = 0;
#pragma unroll
                for (int i = 0; i < DDIM; i++)
#pragma unroll
                    for (int j = i; j < DDIM; j++) acc[k++] += r[i] * r[j];
            }
        }
        __syncthreads();

        t = tn;
        havecur = havenext;
        buf ^= 1;
    }

#pragma unroll
    for (int k = 0; k < NPAIR; k++) {
#pragma unroll
        for (int off = 16; off > 0; off >>= 1)
            acc[k] += __shfl_down_sync(0xffffffffu, acc[k], off);
    }
    int wid = threadIdx.x >> 5, lane = threadIdx.x & 31;
    if (lane == 0) {
#pragma unroll
        for (int k = 0; k < NPAIR; k++) swarp[wid][k] = acc[k];
    }
    __syncthreads();
    if (threadIdx.x < NPAIR) {
        float s = 0.f;
#pragma unroll
        for (int w = 0; w < GTPB / 32; w++) s += swarp[w][threadIdx.x];
        g_part[threadIdx.x][blockIdx.x] = s;
    }
}

// ---------------------------------------------------------------------------
// Fast-approx scalar helpers (sign-safe; ~1e-7 rel err, budget is 1e-3)
// ---------------------------------------------------------------------------
__device__ __forceinline__ float fdivf(float a, float b) { return __fdividef(a, b); }
__device__ __forceinline__ float fsqrta(float x) {
    float r;
    asm("sqrt.approx.f32 %0, %1;" : "=f"(r) : "f"(x));
    return r;
}

// register-array dynamic-index helpers (compile to SEL chains; arrays stay
// in registers because every access is compile-time-indexed after unroll)
__device__ __forceinline__ float rget(const float a[DDIM], int i) {
    float v = a[0];
#pragma unroll
    for (int k = 1; k < DDIM; k++) if (k == i) v = a[k];
    return v;
}
__device__ __forceinline__ void rset(float a[DDIM], int i, float v) {
#pragma unroll
    for (int k = 0; k < DDIM; k++) if (k == i) a[k] = v;
}
// rotate register-Z columns (c0, c1) with LAPACK slasr element formula
__device__ __forceinline__ void zrot(float Z[DDIM], int c0, int c1, float cc, float ss) {
    float t1 = rget(Z, c1), t0 = rget(Z, c0);
    rset(Z, c1, cc * t1 - ss * t0);
    rset(Z, c0, ss * t1 + cc * t0);
}

// ---------------------------------------------------------------------------
// LAPACK-faithful helpers (sign conventions preserved; magnitudes approx)
// ---------------------------------------------------------------------------
__device__ __forceinline__ float lapy2f(float x, float y) {
    float ax = fabsf(x), ay = fabsf(y);
    float w = fmaxf(ax, ay), z = fminf(ax, ay);
    if (z == 0.f) return w;
    float t = fdivf(z, w);
    return w * fsqrta(1.f + t * t);
}
__device__ __forceinline__ float signf(float a, float b) {
    return (b >= 0.f) ? fabsf(a) : -fabsf(a);
}
// LAPACK >= 3.10 slartg convention (c >= 0 always, r = sign(d, f))
__device__ __forceinline__ void lartgf(float f, float g, float& c, float& s, float& r) {
    if (g == 0.f) { c = 1.f; s = 0.f; r = f; }
    else if (f == 0.f) { c = 0.f; s = (g > 0.f) ? 1.f : -1.f; r = fabsf(g); }
    else {
        float d = fsqrta(f * f + g * g);
        c = fdivf(fabsf(f), d);
        r = signf(d, f);
        s = fdivf(g, r);
    }
}
// LAPACK slaev2 (2x2 symmetric eigenproblem with its exact sign logic)
__device__ void laev2f(float a, float b, float c_, float& rt1, float& rt2,
                       float& cs1, float& sn1) {
    float sm = a + c_;
    float df = a - c_;
    float adf = fabsf(df);
    float tb = b + b;
    float ab = fabsf(tb);
    float acmx, acmn;
    if (fabsf(a) > fabsf(c_)) { acmx = a; acmn = c_; } else { acmx = c_; acmn = a; }
    float rt;
    if (adf > ab)      { float q = fdivf(ab, adf); rt = adf * fsqrta(1.f + q * q); }
    else if (adf < ab) { float q = fdivf(adf, ab); rt = ab * fsqrta(1.f + q * q); }
    else               { rt = ab * fsqrta(2.f); }
    int sgn1;
    if (sm < 0.f) {
        rt1 = 0.5f * (sm - rt); sgn1 = -1;
        rt2 = fdivf(acmx, rt1) * acmn - fdivf(b, rt1) * b;
    } else if (sm > 0.f) {
        rt1 = 0.5f * (sm + rt); sgn1 = 1;
        rt2 = fdivf(acmx, rt1) * acmn - fdivf(b, rt1) * b;
    } else {
        rt1 = 0.5f * rt; rt2 = -0.5f * rt; sgn1 = 1;
    }
    float cs; int sgn2;
    if (df >= 0.f) { cs = df + rt; sgn2 = 1; }
    else           { cs = df - rt; sgn2 = -1; }
    float acs = fabsf(cs);
    if (acs > ab) {
        float ct = -fdivf(tb, cs);
        sn1 = rsqrtf(1.f + ct * ct);
        cs1 = ct * sn1;
    } else {
        if (ab == 0.f) { cs1 = 1.f; sn1 = 0.f; }
        else {
            float tn = -fdivf(cs, tb);
            cs1 = rsqrtf(1.f + tn * tn);
            sn1 = tn * cs1;
        }
    }
    if (sgn1 == sgn2) { float tn = cs1; cs1 = -sn1; sn1 = tn; }
}

// ---------------------------------------------------------------------------
// Kernel 2: partial-reduce (8 warps), then warp-0 ssytd2 (smem) + steqr with
// REGISTER-resident D/E/Z (all lanes redundantly run the scalar LAPACK chain;
// each lane's registers hold its Z row; rotations applied inline in the exact
// LAPACK slasr order) + sormtr + MLP.
// ---------------------------------------------------------------------------
__global__ void solve_kernel(const float* __restrict__ W1, const float* __restrict__ b1,
                             const float* __restrict__ W2, const float* __restrict__ b2,
                             float* __restrict__ out) {
    __shared__ float gram[NPAIR];
    __shared__ float Am[DDIM][DDIM];
    __shared__ float Zm[DDIM][DDIM];
    __shared__ float dd[DDIM], ee[DDIM], tauv[DDIM], pv[DDIM];

    const int tid = threadIdx.x;
    const int wrp = tid >> 5;
    const int lane = tid & 31;
    const int n = DDIM;

    // ---- stage 1: tree-reduce partials (all 8 warps) ----
    for (int k = wrp; k < NPAIR; k += 8) {
        float s = 0.f;
        for (int i = lane; i < GGRID; i += 32) s += g_part[k][i];
#pragma unroll
        for (int off = 16; off > 0; off >>= 1)
            s += __shfl_down_sync(0xffffffffu, s, off);
        if (lane == 0) gram[k] = s;
    }
    __syncthreads();
    if (tid >= 32) return;

    // scatter gram into full symmetric Am
    for (int k = lane; k < NPAIR; k += 32) {
        int i = 0, rem = k;
        while (rem >= n - i) { rem -= (n - i); i++; }
        int j = i + rem;
        float v = gram[k];
        Am[i][j] = v;
        Am[j][i] = v;
    }
    __syncwarp();

    // ---------------- ssytd2 (uplo='L'), smem Am ----------------
    for (int i = 0; i < n - 1; i++) {
        float alpha = Am[i + 1][i];
        float xnorm = 0.f;
        for (int r = i + 2; r < n; r++) xnorm += Am[r][i] * Am[r][i];
        xnorm = fsqrta(xnorm);
        float taui = 0.f;
        if (xnorm != 0.f) {
            float beta = -signf(lapy2f(alpha, xnorm), alpha);
            taui = fdivf(beta - alpha, beta);
            float sc = fdivf(1.f, alpha - beta);
            if (lane >= i + 2 && lane < n) Am[lane][i] *= sc;
            if (lane == 0) Am[i + 1][i] = beta;
            __syncwarp();
        }
        ee[i] = Am[i + 1][i];
        if (taui != 0.f) {
            if (lane >= i + 1 && lane < n) {
                int r = lane;
                float s = Am[r][i + 1];
                for (int c = i + 2; c < n; c++) s += Am[r][c] * Am[c][i];
                pv[r] = taui * s;
            }
            __syncwarp();
            float vtp = pv[i + 1];
            for (int r = i + 2; r < n; r++) vtp += pv[r] * Am[r][i];
            float alph = -0.5f * taui * vtp;
            __syncwarp();
            if (lane >= i + 1 && lane < n) {
                if (lane == i + 1) pv[lane] += alph;
                else               pv[lane] += alph * Am[lane][i];
            }
            __syncwarp();
            if (lane >= i + 1 && lane < n) {
                int r = lane;
                float vr = (r == i + 1) ? 1.f : Am[r][i];
                float wr = pv[r];
                for (int c = i + 1; c < n; c++) {
                    float vc = (c == i + 1) ? 1.f : Am[c][i];
                    Am[r][c] -= vr * pv[c] + wr * vc;
                }
            }
            __syncwarp();
        }
        dd[i] = Am[i][i];
        tauv[i] = taui;
        __syncwarp();
    }
    dd[n - 1] = Am[n - 1][n - 1];
    __syncwarp();

    // ---- load D/E/Z into registers (replicated across lanes) ----
    float D[DDIM], E[DDIM], Z[DDIM];
#pragma unroll
    for (int k = 0; k < DDIM; k++) {
        D[k] = dd[k];
        E[k] = (k < DDIM - 1) ? ee[k] : 0.f;
        Z[k] = (lane == k) ? 1.f : 0.f;   // lane owns Z row 'lane'
    }

    // ---------------- ssteqr (compz='I'), fully register-resident ----------
    {
        const float eps = 5.9604645e-8f;
        const float eps2 = eps * eps;
        const float safmin = 1.17549435e-38f;
        const int nmaxit = n * 30;
        int jtot = 0;
        int l1 = 1;
        // 1-based LAPACK indices: Dv(i) = D[i-1], Ev(i) = E[i-1]
        while (l1 <= n) {
            if (l1 > 1) rset(E, l1 - 2, 0.f);
            int m = n;
            {
                bool found = false;
#pragma unroll
                for (int mm = 1; mm <= DDIM - 1; mm++) {
                    if (!found && mm >= l1) {
                        float tst = fabsf(E[mm - 1]);
                        if (tst == 0.f) { m = mm; found = true; }
                        else if (tst <= fsqrta(fabsf(D[mm - 1])) * fsqrta(fabsf(D[mm])) * eps) {
                            E[mm - 1] = 0.f; m = mm; found = true;
                        }
                    }
                }
            }
            int l = l1, lend = m;
            l1 = m + 1;
            if (lend == l) continue;
            float anorm = 0.f;
#pragma unroll
            for (int i = 1; i <= DDIM; i++)
                if (i >= l && i <= lend) anorm = fmaxf(anorm, fabsf(D[i - 1]));
#pragma unroll
            for (int i = 1; i <= DDIM - 1; i++)
                if (i >= l && i <= lend - 1) anorm = fmaxf(anorm, fabsf(E[i - 1]));
            if (anorm == 0.f) continue;
            if (fabsf(rget(D, lend - 1)) < fabsf(rget(D, l - 1))) { int t = l; l = lend; lend = t; }

            if (lend > l) {
                // ---- QL iteration ----
                while (true) {
                    int m2 = lend;
                    if (l != lend) {
                        bool found = false;
#pragma unroll
                        for (int mm = 1; mm <= DDIM - 1; mm++) {
                            if (!found && mm >= l && mm <= lend - 1) {
                                float tst = fabsf(E[mm - 1]); tst = tst * tst;
                                if (tst <= (eps2 * fabsf(D[mm - 1])) * fabsf(D[mm]) + safmin) {
                                    m2 = mm; found = true;
                                }
                            }
                        }
                    }
                    if (m2 < lend) rset(E, m2 - 1, 0.f);
                    float p = rget(D, l - 1);
                    if (m2 == l) {
                        l++;
                        if (l <= lend) continue;
                        break;
                    }
                    if (m2 == l + 1) {
                        float rt1, rt2, cc, ss;
                        laev2f(rget(D, l - 1), rget(E, l - 1), rget(D, l), rt1, rt2, cc, ss);
                        zrot(Z, l - 1, l, cc, ss);           // cols (l-1, l) 0-based
                        rset(D, l - 1, rt1); rset(D, l, rt2); rset(E, l - 1, 0.f);
                        l += 2;
                        if (l <= lend) continue;
                        break;
                    }
                    if (jtot == nmaxit) break;
                    jtot++;
                    float g = fdivf(rget(D, l) - p, 2.f * rget(E, l - 1));
                    float r = lapy2f(g, 1.f);
                    g = rget(D, m2 - 1) - p + fdivf(rget(E, l - 1), g + signf(r, g));
                    float s = 1.f, c = 1.f; p = 0.f;
                    // rotations generated i = m2-1 downto l; LAPACK slasr 'B'
                    // replays them in this same order -> apply inline.
#pragma unroll
                    for (int i = DDIM - 1; i >= 1; i--) {
                        if (i <= m2 - 1 && i >= l) {
                            float f = s * E[i - 1], b = c * E[i - 1];
                            float rr;
                            lartgf(g, f, c, s, rr);
                            if (i != m2 - 1) E[i] = rr;
                            g = D[i] - p;
                            float r2 = (D[i - 1] - g) * s + 2.f * c * b;
                            p = s * r2;
                            D[i] = g + p;
                            g = c * r2 - b;
                            // ct=c, st=-s applied to Z cols (i-1, i):
                            float t1 = Z[i], t0 = Z[i - 1];
                            Z[i]     = c * t1 + s * t0;      // ct*t1 - st*t0
                            Z[i - 1] = -s * t1 + c * t0;     // st*t1 + ct*t0
                        }
                    }
                    rset(D, l - 1, rget(D, l - 1) - p);
                    rset(E, l - 1, g);
                }
            } else {
                // ---- QR iteration ----
                while (true) {
                    int m2 = lend;
                    if (l != lend) {
                        bool found = false;
#pragma unroll
                        for (int mm = DDIM; mm >= 2; mm--) {
                            if (!found && mm <= l && mm >= lend + 1) {
                                float tst = fabsf(E[mm - 2]); tst = tst * tst;
                                if (tst <= (eps2 * fabsf(D[mm - 1])) * fabsf(D[mm - 2]) + safmin) {
                                    m2 = mm; found = true;
                                }
                            }
                        }
                    }
                    if (m2 > lend) rset(E, m2 - 2, 0.f);
                    float p = rget(D, l - 1);
                    if (m2 == l) {
                        l--;
                        if (l >= lend) continue;
                        break;
                    }
                    if (m2 == l - 1) {
                        float rt1, rt2, cc, ss;
                        laev2f(rget(D, l - 2), rget(E, l - 2), rget(D, l - 1), rt1, rt2, cc, ss);
                        zrot(Z, l - 2, l - 1, cc, ss);       // cols (l-2, l-1) 0-based
                        rset(D, l - 2, rt1); rset(D, l - 1, rt2); rset(E, l - 2, 0.f);
                        l -= 2;
                        if (l >= lend) continue;
                        break;
                    }
                    if (jtot == nmaxit) break;
                    jtot++;
                    float g = fdivf(rget(D, l - 2) - p, 2.f * rget(E, l - 2));
                    float r = lapy2f(g, 1.f);
                    g = rget(D, m2 - 1) - p + fdivf(rget(E, l - 2), g + signf(r, g));
                    float s = 1.f, c = 1.f; p = 0.f;
                    // rotations generated i = m2 .. l-1; slasr 'F' replays in
                    // the same ascending order -> apply inline.
#pragma unroll
                    for (int i = 1; i <= DDIM - 1; i++) {
                        if (i >= m2 && i <= l - 1) {
                            float f = s * E[i - 1], b = c * E[i - 1];
                            float rr;
                            lartgf(g, f, c, s, rr);
                            if (i >= 2 && i != m2) E[i - 2] = rr;
                            g = D[i - 1] - p;
                            float r2 = (D[i] - g) * s + 2.f * c * b;
                            p = s * r2;
                            D[i - 1] = g + p;
                            g = c * r2 - b;
                            // ct=c, st=s applied to Z cols (i-1, i):
                            float t1 = Z[i], t0 = Z[i - 1];
                            Z[i]     = c * t1 - s * t0;
                            Z[i - 1] = s * t1 + c * t0;
                        }
                    }
                    rset(D, l - 1, rget(D, l - 1) - p);
                    rset(E, l - 2, g);
                }
            }
        }

        // selection sort ascending + Z column swaps (register selects)
#pragma unroll
        for (int ii = 2; ii <= DDIM; ii++) {
            int k = ii - 1;
            float p = D[ii - 2];
#pragma unroll
            for (int j = 2; j <= DDIM; j++) {
                if (j >= ii) {
                    float dj = D[j - 1];
                    if (dj < p) { k = j; p = dj; }
                }
            }
            if (k != ii - 1) {
                rset(D, k - 1, D[ii - 2]);
                D[ii - 2] = p;
                float t = Z[ii - 2];
                Z[ii - 2] = rget(Z, k - 1);
                rset(Z, k - 1, t);
            }
        }
    }

    // dump register Z rows to smem for the column-owned sormtr pass
    if (lane < n) {
#pragma unroll
        for (int k = 0; k < DDIM; k++) Zm[lane][k] = Z[k];
    }
    __syncwarp();

    // ---------------- sormtr: Z := H(1)...H(n-1) Z ; lane owns column ----
    for (int i = n - 2; i >= 0; i--) {
        if (tauv[i] == 0.f) continue;
        if (lane < n) {
            int c = lane;
            float s = Zm[i + 1][c];
            for (int r = i + 2; r < n; r++) s += Am[r][i] * Zm[r][c];
            s *= tauv[i];
            Zm[i + 1][c] -= s;
            for (int r = i + 2; r < n; r++) Zm[r][c] -= s * Am[r][i];
        }
    }
    __syncwarp();   // back to row reads for the MLP

    // ---------------- MLP: relu(w @ W1^T + b1) @ W2^T + b2; 0.5*(sigmoid+1)
    if (lane < n) {
        float zr[DDIM];
#pragma unroll
        for (int k = 0; k < DDIM; k++) zr[k] = Zm[lane][k];
        float y2 = b2[0];
        for (int h = 0; h < HID; h++) {
            float a = b1[h];
#pragma unroll
            for (int k = 0; k < DDIM; k++) a += zr[k] * W1[h * DDIM + k];
            a = fmaxf(a, 0.f);
            y2 += a * W2[h];
        }
        out[lane] = 0.5f * (fdivf(1.f, 1.f + __expf(-y2)) + 1.f);
    }
}

// ---------------------------------------------------------------------------
extern "C" void kernel_launch(void* const* d_in, const int* in_sizes, int n_in,
                              void* d_out, int out_size) {
    const float* x  = (const float*)d_in[0];
    const float* W1 = (const float*)d_in[1];
    const float* b1 = (const float*)d_in[2];
    const float* W2 = (const float*)d_in[3];
    const float* b2 = (const float*)d_in[4];
    long long nrows = (long long)in_sizes[0] / DDIM;

    gram_kernel<<<GGRID, GTPB>>>(x, nrows);
    solve_kernel<<<1, GTPB>>>(W1, b1, W2, b2, (float*)d_out);
}

// round 9
// speedup vs baseline: 1.1542x; 1.0644x over previous
#include <cuda_runtime.h>
#include <cstdint>

#define DDIM 10
#define NPAIR 55
#define GTPB 256
#define GGRID 296            // 148 SMs x 2 blocks -> one full wave
#define ROWS_TILE 512        // rows per tile (2 rows / thread)
#define TILE_F4 (ROWS_TILE * DDIM / 4)   // 1280 float4 per tile
#define TILE_FLOATS (ROWS_TILE * DDIM)   // 5120 floats per tile
#define HID 16

// lower-triangle linear index, r >= c  (matches gram pair ordering)
#define TIX(r, c) ((c) * DDIM - ((c) * ((c) - 1)) / 2 + ((r) - (c)))

// Deterministic two-stage reduction scratch (no atomics, no allocation).
__device__ float g_part[NPAIR][GGRID];

// ---------------------------------------------------------------------------
// async-copy helpers
// ---------------------------------------------------------------------------
__device__ __forceinline__ void cp_async16(uint32_t smem_dst, const void* gsrc) {
    asm volatile("cp.async.cg.shared.global [%0], [%1], 16;\n"
                 :: "r"(smem_dst), "l"(gsrc));
}
__device__ __forceinline__ void cp_commit() {
    asm volatile("cp.async.commit_group;\n");
}
__device__ __forceinline__ void cp_wait0() {
    asm volatile("cp.async.wait_group 0;\n");
}
__device__ __forceinline__ void cp_wait1() {
    asm volatile("cp.async.wait_group 1;\n");
}

// ---------------------------------------------------------------------------
// Kernel 1: Gram partials. At the HBM roofline (~20us) — unchanged.
// ---------------------------------------------------------------------------
__global__ void __launch_bounds__(GTPB, 2)
gram_kernel(const float* __restrict__ x, long long nrows) {
    __shared__ __align__(16) float sbuf[2][TILE_FLOATS];
    __shared__ float swarp[GTPB / 32][NPAIR];

    float acc[NPAIR];
#pragma unroll
    for (int k = 0; k < NPAIR; k++) acc[k] = 0.f;

    const long long ntiles = (nrows + ROWS_TILE - 1) / ROWS_TILE;
    const long long totalf4 = nrows * (long long)DDIM / 4;
    const float4* xsrc = reinterpret_cast<const float4*>(x);
    const uint32_t sbase = (uint32_t)__cvta_generic_to_shared(&sbuf[0][0]);

    long long t = blockIdx.x;
    bool havecur = (t < ntiles);

    if (havecur) {
        long long base4 = t * (long long)TILE_F4;
#pragma unroll
        for (int j = 0; j < TILE_F4 / GTPB; j++) {
            int i = threadIdx.x + j * GTPB;
            long long g4 = base4 + i;
            if (g4 < totalf4) {
                cp_async16(sbase + (uint32_t)i * 16u, xsrc + g4);
            } else {
                float4 z = make_float4(0.f, 0.f, 0.f, 0.f);
                reinterpret_cast<float4*>(&sbuf[0][0])[i] = z;
            }
        }
        cp_commit();
    }

    int buf = 0;
    while (havecur) {
        long long tn = t + (long long)GGRID;
        bool havenext = (tn < ntiles);
        if (havenext) {
            long long base4 = tn * (long long)TILE_F4;
            uint32_t dbase = sbase + (uint32_t)(buf ^ 1) * (TILE_FLOATS * 4u);
#pragma unroll
            for (int j = 0; j < TILE_F4 / GTPB; j++) {
                int i = threadIdx.x + j * GTPB;
                long long g4 = base4 + i;
                if (g4 < totalf4) {
                    cp_async16(dbase + (uint32_t)i * 16u, xsrc + g4);
                } else {
                    float4 z = make_float4(0.f, 0.f, 0.f, 0.f);
                    reinterpret_cast<float4*>(&sbuf[buf ^ 1][0])[i] = z;
                }
            }
            cp_commit();
            cp_wait1();
        } else {
            cp_wait0();
        }
        __syncthreads();

        const float* sb = &sbuf[buf][0];
#pragma unroll
        for (int half = 0; half < 2; half++) {
            int r0 = threadIdx.x + half * GTPB;
            long long row_g = t * (long long)ROWS_TILE + r0;
            if (row_g < nrows) {
                float r[DDIM];
                const float2* rp = reinterpret_cast<const float2*>(sb + r0 * DDIM);
#pragma unroll
                for (int j = 0; j < 5; j++) {
                    float2 v = rp[j];
                    r[2 * j] = v.x;
                    r[2 * j + 1] = v.y;
                }
                int k = 0;
#pragma unroll
                for (int i = 0; i < DDIM; i++)
#pragma unroll
                    for (int j = i; j < DDIM; j++) acc[k++] += r[i] * r[j];
            }
        }
        __syncthreads();

        t = tn;
        havecur = havenext;
        buf ^= 1;
    }

#pragma unroll
    for (int k = 0; k < NPAIR; k++) {
#pragma unroll
        for (int off = 16; off > 0; off >>= 1)
            acc[k] += __shfl_down_sync(0xffffffffu, acc[k], off);
    }
    int wid = threadIdx.x >> 5, lane = threadIdx.x & 31;
    if (lane == 0) {
#pragma unroll
        for (int k = 0; k < NPAIR; k++) swarp[wid][k] = acc[k];
    }
    __syncthreads();
    if (threadIdx.x < NPAIR) {
        float s = 0.f;
#pragma unroll
        for (int w = 0; w < GTPB / 32; w++) s += swarp[w][threadIdx.x];
        g_part[threadIdx.x][blockIdx.x] = s;
    }
}

// ---------------------------------------------------------------------------
// Fast-approx scalar helpers (sign-safe; ~1e-7 rel err, budget is 1e-3)
// ---------------------------------------------------------------------------
__device__ __forceinline__ float fdivf(float a, float b) { return __fdividef(a, b); }
__device__ __forceinline__ float fsqrta(float x) {
    float r;
    asm("sqrt.approx.f32 %0, %1;" : "=f"(r) : "f"(x));
    return r;
}

// register-array dynamic-index helpers (SEL chains; used only in steqr/sort)
__device__ __forceinline__ float rget(const float a[DDIM], int i) {
    float v = a[0];
#pragma unroll
    for (int k = 1; k < DDIM; k++) if (k == i) v = a[k];
    return v;
}
__device__ __forceinline__ void rset(float a[DDIM], int i, float v) {
#pragma unroll
    for (int k = 0; k < DDIM; k++) if (k == i) a[k] = v;
}
__device__ __forceinline__ void zrot(float Z[DDIM], int c0, int c1, float cc, float ss) {
    float t1 = rget(Z, c1), t0 = rget(Z, c0);
    rset(Z, c1, cc * t1 - ss * t0);
    rset(Z, c0, ss * t1 + cc * t0);
}

// ---------------------------------------------------------------------------
// LAPACK-faithful helpers (sign conventions preserved; magnitudes approx)
// ---------------------------------------------------------------------------
__device__ __forceinline__ float lapy2f(float x, float y) {
    float ax = fabsf(x), ay = fabsf(y);
    float w = fmaxf(ax, ay), z = fminf(ax, ay);
    if (z == 0.f) return w;
    float t = fdivf(z, w);
    return w * fsqrta(1.f + t * t);
}
__device__ __forceinline__ float signf(float a, float b) {
    return (b >= 0.f) ? fabsf(a) : -fabsf(a);
}
// LAPACK >= 3.10 slartg convention (c >= 0 always, r = sign(d, f))
__device__ __forceinline__ void lartgf(float f, float g, float& c, float& s, float& r) {
    if (g == 0.f) { c = 1.f; s = 0.f; r = f; }
    else if (f == 0.f) { c = 0.f; s = (g > 0.f) ? 1.f : -1.f; r = fabsf(g); }
    else {
        float d = fsqrta(f * f + g * g);
        c = fdivf(fabsf(f), d);
        r = signf(d, f);
        s = fdivf(g, r);
    }
}
// LAPACK slaev2 (2x2 symmetric eigenproblem with its exact sign logic)
__device__ void laev2f(float a, float b, float c_, float& rt1, float& rt2,
                       float& cs1, float& sn1) {
    float sm = a + c_;
    float df = a - c_;
    float adf = fabsf(df);
    float tb = b + b;
    float ab = fabsf(tb);
    float acmx, acmn;
    if (fabsf(a) > fabsf(c_)) { acmx = a; acmn = c_; } else { acmx = c_; acmn = a; }
    float rt;
    if (adf > ab)      { float q = fdivf(ab, adf); rt = adf * fsqrta(1.f + q * q); }
    else if (adf < ab) { float q = fdivf(adf, ab); rt = ab * fsqrta(1.f + q * q); }
    else               { rt = ab * fsqrta(2.f); }
    int sgn1;
    if (sm < 0.f) {
        rt1 = 0.5f * (sm - rt); sgn1 = -1;
        rt2 = fdivf(acmx, rt1) * acmn - fdivf(b, rt1) * b;
    } else if (sm > 0.f) {
        rt1 = 0.5f * (sm + rt); sgn1 = 1;
        rt2 = fdivf(acmx, rt1) * acmn - fdivf(b, rt1) * b;
    } else {
        rt1 = 0.5f * rt; rt2 = -0.5f * rt; sgn1 = 1;
    }
    float cs; int sgn2;
    if (df >= 0.f) { cs = df + rt; sgn2 = 1; }
    else           { cs = df - rt; sgn2 = -1; }
    float acs = fabsf(cs);
    if (acs > ab) {
        float ct = -fdivf(tb, cs);
        sn1 = rsqrtf(1.f + ct * ct);
        cs1 = ct * sn1;
    } else {
        if (ab == 0.f) { cs1 = 1.f; sn1 = 0.f; }
        else {
            float tn = -fdivf(cs, tb);
            cs1 = rsqrtf(1.f + tn * tn);
            sn1 = tn * cs1;
        }
    }
    if (sgn1 == sgn2) { float tn = cs1; cs1 = -sn1; sn1 = tn; }
}

// symmetric access into lower-triangle register array (compile-time indices)
#define AGET(A, r, c) (((r) >= (c)) ? (A)[TIX((r), (c))] : (A)[TIX((c), (r))])

// ---------------------------------------------------------------------------
// Kernel 2: partial-reduce (8 warps), then warp 0 runs the WHOLE eigh in
// registers: A as replicated 55-reg lower triangle (ssytd2 fully unrolled,
// zero smem/syncwarp), register steqr (as before), register sormtr via two
// tiny smem transposes, MLP. Arithmetic order identical to the passing
// version -> identical LAPACK sign decisions.
// ---------------------------------------------------------------------------
__global__ void solve_kernel(const float* __restrict__ W1, const float* __restrict__ b1,
                             const float* __restrict__ W2, const float* __restrict__ b2,
                             float* __restrict__ out) {
    __shared__ float gram[NPAIR];
    __shared__ float Zm[DDIM][DDIM];

    const int tid = threadIdx.x;
    const int wrp = tid >> 5;
    const int lane = tid & 31;
    const int n = DDIM;

    // ---- stage 1: tree-reduce partials (all 8 warps) ----
    for (int k = wrp; k < NPAIR; k += 8) {
        float s = 0.f;
        for (int i = lane; i < GGRID; i += 32) s += g_part[k][i];
#pragma unroll
        for (int off = 16; off > 0; off >>= 1)
            s += __shfl_down_sync(0xffffffffu, s, off);
        if (lane == 0) gram[k] = s;
    }
    __syncthreads();
    if (tid >= 32) return;

    // ---- load gram into replicated lower-triangle registers ----
    float At[NPAIR];
#pragma unroll
    for (int k = 0; k < NPAIR; k++) At[k] = gram[k];   // broadcast LDS

    float D[DDIM], E[DDIM], Tau[DDIM - 1];

    // ---------------- ssytd2 (uplo='L'), fully register-resident ----------
#pragma unroll
    for (int i = 0; i < DDIM - 1; i++) {
        float alpha = At[TIX(i + 1, i)];
        float xnorm = 0.f;
#pragma unroll
        for (int r = i + 2; r < DDIM; r++) xnorm += At[TIX(r, i)] * At[TIX(r, i)];
        xnorm = fsqrta(xnorm);
        float taui = 0.f;
        if (xnorm != 0.f) {
            float beta = -signf(lapy2f(alpha, xnorm), alpha);
            taui = fdivf(beta - alpha, beta);
            float sc = fdivf(1.f, alpha - beta);
#pragma unroll
            for (int r = i + 2; r < DDIM; r++) At[TIX(r, i)] *= sc;
            At[TIX(i + 1, i)] = beta;
        }
        E[i] = At[TIX(i + 1, i)];
        if (taui != 0.f) {
            float pv[DDIM];
#pragma unroll
            for (int r = i + 1; r < DDIM; r++) {
                float s = AGET(At, r, i + 1);
#pragma unroll
                for (int c = i + 2; c < DDIM; c++) s += AGET(At, r, c) * At[TIX(c, i)];
                pv[r] = taui * s;
            }
            float vtp = pv[i + 1];
#pragma unroll
            for (int r = i + 2; r < DDIM; r++) vtp += pv[r] * At[TIX(r, i)];
            float alph = -0.5f * taui * vtp;
            pv[i + 1] += alph;
#pragma unroll
            for (int r = i + 2; r < DDIM; r++) pv[r] += alph * At[TIX(r, i)];
            // rank-2 update on the lower triangle (r >= c >= i+1)
#pragma unroll
            for (int r = i + 1; r < DDIM; r++) {
                float vr = (r == i + 1) ? 1.f : At[TIX(r, i)];
                float wr = pv[r];
#pragma unroll
                for (int c = i + 1; c <= r; c++) {
                    float vc = (c == i + 1) ? 1.f : At[TIX(c, i)];
                    At[TIX(r, c)] -= vr * pv[c] + wr * vc;
                }
            }
        }
        D[i] = At[TIX(i, i)];
        Tau[i] = taui;
    }
    D[DDIM - 1] = At[TIX(DDIM - 1, DDIM - 1)];
    E[DDIM - 1] = 0.f;

    // lane owns Z row 'lane' in registers
    float Z[DDIM];
#pragma unroll
    for (int k = 0; k < DDIM; k++) Z[k] = (lane == k) ? 1.f : 0.f;

    // ---------------- ssteqr (compz='I'), fully register-resident ----------
    {
        const float eps = 5.9604645e-8f;
        const float eps2 = eps * eps;
        const float safmin = 1.17549435e-38f;
        const int nmaxit = n * 30;
        int jtot = 0;
        int l1 = 1;
        while (l1 <= n) {
            if (l1 > 1) rset(E, l1 - 2, 0.f);
            int m = n;
            {
                bool found = false;
#pragma unroll
                for (int mm = 1; mm <= DDIM - 1; mm++) {
                    if (!found && mm >= l1) {
                        float tst = fabsf(E[mm - 1]);
                        if (tst == 0.f) { m = mm; found = true; }
                        else if (tst <= fsqrta(fabsf(D[mm - 1])) * fsqrta(fabsf(D[mm])) * eps) {
                            E[mm - 1] = 0.f; m = mm; found = true;
                        }
                    }
                }
            }
            int l = l1, lend = m;
            l1 = m + 1;
            if (lend == l) continue;
            float anorm = 0.f;
#pragma unroll
            for (int i = 1; i <= DDIM; i++)
                if (i >= l && i <= lend) anorm = fmaxf(anorm, fabsf(D[i - 1]));
#pragma unroll
            for (int i = 1; i <= DDIM - 1; i++)
                if (i >= l && i <= lend - 1) anorm = fmaxf(anorm, fabsf(E[i - 1]));
            if (anorm == 0.f) continue;
            if (fabsf(rget(D, lend - 1)) < fabsf(rget(D, l - 1))) { int t = l; l = lend; lend = t; }

            if (lend > l) {
                // ---- QL iteration ----
                while (true) {
                    int m2 = lend;
                    if (l != lend) {
                        bool found = false;
#pragma unroll
                        for (int mm = 1; mm <= DDIM - 1; mm++) {
                            if (!found && mm >= l && mm <= lend - 1) {
                                float tst = fabsf(E[mm - 1]); tst = tst * tst;
                                if (tst <= (eps2 * fabsf(D[mm - 1])) * fabsf(D[mm]) + safmin) {
                                    m2 = mm; found = true;
                                }
                            }
                        }
                    }
                    if (m2 < lend) rset(E, m2 - 1, 0.f);
                    float p = rget(D, l - 1);
                    if (m2 == l) {
                        l++;
                        if (l <= lend) continue;
                        break;
                    }
                    if (m2 == l + 1) {
                        float rt1, rt2, cc, ss;
                        laev2f(rget(D, l - 1), rget(E, l - 1), rget(D, l), rt1, rt2, cc, ss);
                        zrot(Z, l - 1, l, cc, ss);
                        rset(D, l - 1, rt1); rset(D, l, rt2); rset(E, l - 1, 0.f);
                        l += 2;
                        if (l <= lend) continue;
                        break;
                    }
                    if (jtot == nmaxit) break;
                    jtot++;
                    float g = fdivf(rget(D, l) - p, 2.f * rget(E, l - 1));
                    float r = lapy2f(g, 1.f);
                    g = rget(D, m2 - 1) - p + fdivf(rget(E, l - 1), g + signf(r, g));
                    float s = 1.f, c = 1.f; p = 0.f;
#pragma unroll
                    for (int i = DDIM - 1; i >= 1; i--) {
                        if (i <= m2 - 1 && i >= l) {
                            float f = s * E[i - 1], b = c * E[i - 1];
                            float rr;
                            lartgf(g, f, c, s, rr);
                            if (i != m2 - 1) E[i] = rr;
                            g = D[i] - p;
                            float r2 = (D[i - 1] - g) * s + 2.f * c * b;
                            p = s * r2;
                            D[i] = g + p;
                            g = c * r2 - b;
                            float t1 = Z[i], t0 = Z[i - 1];
                            Z[i]     = c * t1 + s * t0;
                            Z[i - 1] = -s * t1 + c * t0;
                        }
                    }
                    rset(D, l - 1, rget(D, l - 1) - p);
                    rset(E, l - 1, g);
                }
            } else {
                // ---- QR iteration ----
                while (true) {
                    int m2 = lend;
                    if (l != lend) {
                        bool found = false;
#pragma unroll
                        for (int mm = DDIM; mm >= 2; mm--) {
                            if (!found && mm <= l && mm >= lend + 1) {
                                float tst = fabsf(E[mm - 2]); tst = tst * tst;
                                if (tst <= (eps2 * fabsf(D[mm - 1])) * fabsf(D[mm - 2]) + safmin) {
                                    m2 = mm; found = true;
                                }
                            }
                        }
                    }
                    if (m2 > lend) rset(E, m2 - 2, 0.f);
                    float p = rget(D, l - 1);
                    if (m2 == l) {
                        l--;
                        if (l >= lend) continue;
                        break;
                    }
                    if (m2 == l - 1) {
                        float rt1, rt2, cc, ss;
                        laev2f(rget(D, l - 2), rget(E, l - 2), rget(D, l - 1), rt1, rt2, cc, ss);
                        zrot(Z, l - 2, l - 1, cc, ss);
                        rset(D, l - 2, rt1); rset(D, l - 1, rt2); rset(E, l - 2, 0.f);
                        l -= 2;
                        if (l >= lend) continue;
                        break;
                    }
                    if (jtot == nmaxit) break;
                    jtot++;
                    float g = fdivf(rget(D, l - 2) - p, 2.f * rget(E, l - 2));
                    float r = lapy2f(g, 1.f);
                    g = rget(D, m2 - 1) - p + fdivf(rget(E, l - 2), g + signf(r, g));
                    float s = 1.f, c = 1.f; p = 0.f;
#pragma unroll
                    for (int i = 1; i <= DDIM - 1; i++) {
                        if (i >= m2 && i <= l - 1) {
                            float f = s * E[i - 1], b = c * E[i - 1];
                            float rr;
                            lartgf(g, f, c, s, rr);
                            if (i >= 2 && i != m2) E[i - 2] = rr;
                            g = D[i - 1] - p;
                            float r2 = (D[i] - g) * s + 2.f * c * b;
                            p = s * r2;
                            D[i - 1] = g + p;
                            g = c * r2 - b;
                            float t1 = Z[i], t0 = Z[i - 1];
                            Z[i]     = c * t1 - s * t0;
                            Z[i - 1] = s * t1 + c * t0;
                        }
                    }
                    rset(D, l - 1, rget(D, l - 1) - p);
                    rset(E, l - 2, g);
                }
            }
        }

        // selection sort ascending + Z column swaps
#pragma unroll
        for (int ii = 2; ii <= DDIM; ii++) {
            int k = ii - 1;
            float p = D[ii - 2];
#pragma unroll
            for (int j = 2; j <= DDIM; j++) {
                if (j >= ii) {
                    float dj = D[j - 1];
                    if (dj < p) { k = j; p = dj; }
                }
            }
            if (k != ii - 1) {
                rset(D, k - 1, D[ii - 2]);
                D[ii - 2] = p;
                float t = Z[ii - 2];
                Z[ii - 2] = rget(Z, k - 1);
                rset(Z, k - 1, t);
            }
        }
    }

    // ---- transpose Z (row-owned regs -> column-owned regs) via smem ----
    if (lane < n) {
#pragma unroll
        for (int k = 0; k < DDIM; k++) Zm[lane][k] = Z[k];
    }
    __syncwarp();
    const int cc = (lane < n) ? lane : 0;
    float Zc[DDIM];
#pragma unroll
    for (int r = 0; r < DDIM; r++) Zc[r] = Zm[r][cc];

    // ---------------- sormtr in registers: Z := H(1)...H(n-1) Z ----------
#pragma unroll
    for (int i = DDIM - 2; i >= 0; i--) {
        if (Tau[i] != 0.f) {
            float s = Zc[i + 1];
#pragma unroll
            for (int r = i + 2; r < DDIM; r++) s += At[TIX(r, i)] * Zc[r];
            s *= Tau[i];
            Zc[i + 1] -= s;
#pragma unroll
            for (int r = i + 2; r < DDIM; r++) Zc[r] -= s * At[TIX(r, i)];
        }
    }

    // ---- transpose back (column-owned -> row reads) via smem ----
    __syncwarp();
    if (lane < n) {
#pragma unroll
        for (int r = 0; r < DDIM; r++) Zm[r][lane] = Zc[r];
    }
    __syncwarp();

    // ---------------- MLP: relu(w @ W1^T + b1) @ W2^T + b2; 0.5*(sigmoid+1)
    if (lane < n) {
        float zr[DDIM];
#pragma unroll
        for (int k = 0; k < DDIM; k++) zr[k] = Zm[lane][k];
        float y2 = b2[0];
        for (int h = 0; h < HID; h++) {
            float a = b1[h];
#pragma unroll
            for (int k = 0; k < DDIM; k++) a += zr[k] * W1[h * DDIM + k];
            a = fmaxf(a, 0.f);
            y2 += a * W2[h];
        }
        out[lane] = 0.5f * (fdivf(1.f, 1.f + __expf(-y2)) + 1.f);
    }
}

// ---------------------------------------------------------------------------
extern "C" void kernel_launch(void* const* d_in, const int* in_sizes, int n_in,
                              void* d_out, int out_size) {
    const float* x  = (const float*)d_in[0];
    const float* W1 = (const float*)d_in[1];
    const float* b1 = (const float*)d_in[2];
    const float* W2 = (const float*)d_in[3];
    const float* b2 = (const float*)d_in[4];
    long long nrows = (long long)in_sizes[0] / DDIM;

    gram_kernel<<<GGRID, GTPB>>>(x, nrows);
    solve_kernel<<<1, GTPB>>>(W1, b1, W2, b2, (float*)d_out);
}

// round 11
// speedup vs baseline: 1.1900x; 1.0310x over previous
#include <cuda_runtime.h>
#include <cstdint>

#define DDIM 10
#define NPAIR 55
#define GTPB 256
#define GGRID 296            // 148 SMs x 2 blocks -> one full wave
#define ROWS_TILE 512
#define TILE_F4 (ROWS_TILE * DDIM / 4)
#define TILE_FLOATS (ROWS_TILE * DDIM)
#define HID 16
#define FULLM 0xffffffffu

// Deterministic two-stage reduction scratch (no atomics, no allocation).
__device__ float g_part[NPAIR][GGRID];

// ---------------------------------------------------------------------------
// async-copy helpers
// ---------------------------------------------------------------------------
__device__ __forceinline__ void cp_async16(uint32_t smem_dst, const void* gsrc) {
    asm volatile("cp.async.cg.shared.global [%0], [%1], 16;\n"
                 :: "r"(smem_dst), "l"(gsrc));
}
__device__ __forceinline__ void cp_commit() { asm volatile("cp.async.commit_group;\n"); }
__device__ __forceinline__ void cp_wait0() { asm volatile("cp.async.wait_group 0;\n"); }
__device__ __forceinline__ void cp_wait1() { asm volatile("cp.async.wait_group 1;\n"); }

// ---------------------------------------------------------------------------
// Kernel 1: Gram partials. At the HBM roofline — unchanged since R6.
// ---------------------------------------------------------------------------
__global__ void __launch_bounds__(GTPB, 2)
gram_kernel(const float* __restrict__ x, long long nrows) {
    __shared__ __align__(16) float sbuf[2][TILE_FLOATS];
    __shared__ float swarp[GTPB / 32][NPAIR];

    float acc[NPAIR];
#pragma unroll
    for (int k = 0; k < NPAIR; k++) acc[k] = 0.f;

    const long long ntiles = (nrows + ROWS_TILE - 1) / ROWS_TILE;
    const long long totalf4 = nrows * (long long)DDIM / 4;
    const float4* xsrc = reinterpret_cast<const float4*>(x);
    const uint32_t sbase = (uint32_t)__cvta_generic_to_shared(&sbuf[0][0]);

    long long t = blockIdx.x;
    bool havecur = (t < ntiles);

    if (havecur) {
        long long base4 = t * (long long)TILE_F4;
#pragma unroll
        for (int j = 0; j < TILE_F4 / GTPB; j++) {
            int i = threadIdx.x + j * GTPB;
            long long g4 = base4 + i;
            if (g4 < totalf4) {
                cp_async16(sbase + (uint32_t)i * 16u, xsrc + g4);
            } else {
                float4 z = make_float4(0.f, 0.f, 0.f, 0.f);
                reinterpret_cast<float4*>(&sbuf[0][0])[i] = z;
            }
        }
        cp_commit();
    }

    int buf = 0;
    while (havecur) {
        long long tn = t + (long long)GGRID;
        bool havenext = (tn < ntiles);
        if (havenext) {
            long long base4 = tn * (long long)TILE_F4;
            uint32_t dbase = sbase + (uint32_t)(buf ^ 1) * (TILE_FLOATS * 4u);
#pragma unroll
            for (int j = 0; j < TILE_F4 / GTPB; j++) {
                int i = threadIdx.x + j * GTPB;
                long long g4 = base4 + i;
                if (g4 < totalf4) {
                    cp_async16(dbase + (uint32_t)i * 16u, xsrc + g4);
                } else {
                    float4 z = make_float4(0.f, 0.f, 0.f, 0.f);
                    reinterpret_cast<float4*>(&sbuf[buf ^ 1][0])[i] = z;
                }
            }
            cp_commit();
            cp_wait1();
        } else {
            cp_wait0();
        }
        __syncthreads();

        const float* sb = &sbuf[buf][0];
#pragma unroll
        for (int half = 0; half < 2; half++) {
            int r0 = threadIdx.x + half * GTPB;
            long long row_g = t * (long long)ROWS_TILE + r0;
            if (row_g < nrows) {
                float r[DDIM];
                const float2* rp = reinterpret_cast<const float2*>(sb + r0 * DDIM);
#pragma unroll
                for (int j = 0; j < 5; j++) {
                    float2 v = rp[j];
                    r[2 * j] = v.x;
                    r[2 * j + 1] = v.y;
                }
                int k = 0;
#pragma unroll
                for (int i = 0; i < DDIM; i++)
#pragma unroll
                    for (int j = i; j < DDIM; j++) acc[k++] += r[i] * r[j];
            }
        }
        __syncthreads();

        t = tn;
        havecur = havenext;
        buf ^= 1;
    }

#pragma unroll
    for (int k = 0; k < NPAIR; k++) {
#pragma unroll
        for (int off = 16; off > 0; off >>= 1)
            acc[k] += __shfl_down_sync(FULLM, acc[k], off);
    }
    int wid = threadIdx.x >> 5, lane = threadIdx.x & 31;
    if (lane == 0) {
#pragma unroll
        for (int k = 0; k < NPAIR; k++) swarp[wid][k] = acc[k];
    }
    __syncthreads();
    if (threadIdx.x < NPAIR) {
        float s = 0.f;
#pragma unroll
        for (int w = 0; w < GTPB / 32; w++) s += swarp[w][threadIdx.x];
        g_part[threadIdx.x][blockIdx.x] = s;
    }
}

// ---------------------------------------------------------------------------
// Fast-approx scalar helpers (sign-safe)
// ---------------------------------------------------------------------------
__device__ __forceinline__ float fdivf(float a, float b) { return __fdividef(a, b); }
__device__ __forceinline__ float fsqrta(float x) {
    float r;
    asm("sqrt.approx.f32 %0, %1;" : "=f"(r) : "f"(x));
    return r;
}

// register-array dynamic-index helpers (SEL chains; steqr/sort only)
__device__ __forceinline__ float rget(const float a[DDIM], int i) {
    float v = a[0];
#pragma unroll
    for (int k = 1; k < DDIM; k++) if (k == i) v = a[k];
    return v;
}
__device__ __forceinline__ void rset(float a[DDIM], int i, float v) {
#pragma unroll
    for (int k = 0; k < DDIM; k++) if (k == i) a[k] = v;
}
__device__ __forceinline__ void zrot(float Z[DDIM], int c0, int c1, float cc, float ss) {
    float t1 = rget(Z, c1), t0 = rget(Z, c0);
    rset(Z, c1, cc * t1 - ss * t0);
    rset(Z, c0, ss * t1 + cc * t0);
}

// ---------------------------------------------------------------------------
// LAPACK-faithful helpers (sign conventions preserved; magnitudes approx)
// ---------------------------------------------------------------------------
__device__ __forceinline__ float lapy2f(float x, float y) {
    float ax = fabsf(x), ay = fabsf(y);
    float w = fmaxf(ax, ay), z = fminf(ax, ay);
    if (z == 0.f) return w;
    float t = fdivf(z, w);
    return w * fsqrta(1.f + t * t);
}
__device__ __forceinline__ float signf(float a, float b) {
    return (b >= 0.f) ? fabsf(a) : -fabsf(a);
}
// LAPACK >= 3.10 slartg convention
__device__ __forceinline__ void lartgf(float f, float g, float& c, float& s, float& r) {
    if (g == 0.f) { c = 1.f; s = 0.f; r = f; }
    else if (f == 0.f) { c = 0.f; s = (g > 0.f) ? 1.f : -1.f; r = fabsf(g); }
    else {
        float d = fsqrta(f * f + g * g);
        c = fdivf(fabsf(f), d);
        r = signf(d, f);
        s = fdivf(g, r);
    }
}
// LAPACK slaev2
__device__ void laev2f(float a, float b, float c_, float& rt1, float& rt2,
                       float& cs1, float& sn1) {
    float sm = a + c_;
    float df = a - c_;
    float adf = fabsf(df);
    float tb = b + b;
    float ab = fabsf(tb);
    float acmx, acmn;
    if (fabsf(a) > fabsf(c_)) { acmx = a; acmn = c_; } else { acmx = c_; acmn = a; }
    float rt;
    if (adf > ab)      { float q = fdivf(ab, adf); rt = adf * fsqrta(1.f + q * q); }
    else if (adf < ab) { float q = fdivf(adf, ab); rt = ab * fsqrta(1.f + q * q); }
    else               { rt = ab * fsqrta(2.f); }
    int sgn1;
    if (sm < 0.f) {
        rt1 = 0.5f * (sm - rt); sgn1 = -1;
        rt2 = fdivf(acmx, rt1) * acmn - fdivf(b, rt1) * b;
    } else if (sm > 0.f) {
        rt1 = 0.5f * (sm + rt); sgn1 = 1;
        rt2 = fdivf(acmx, rt1) * acmn - fdivf(b, rt1) * b;
    } else {
        rt1 = 0.5f * rt; rt2 = -0.5f * rt; sgn1 = 1;
    }
    float cs; int sgn2;
    if (df >= 0.f) { cs = df + rt; sgn2 = 1; }
    else           { cs = df - rt; sgn2 = -1; }
    float acs = fabsf(cs);
    if (acs > ab) {
        float ct = -fdivf(tb, cs);
        sn1 = rsqrtf(1.f + ct * ct);
        cs1 = ct * sn1;
    } else {
        if (ab == 0.f) { cs1 = 1.f; sn1 = 0.f; }
        else {
            float tn = -fdivf(cs, tb);
            cs1 = rsqrtf(1.f + tn * tn);
            sn1 = tn * cs1;
        }
    }
    if (sgn1 == sgn2) { float tn = cs1; cs1 = -sn1; sn1 = tn; }
}

// ---------------------------------------------------------------------------
// Kernel 2: 8-warp partial reduce, then warp 0:
//   ssytd2  : lane-owns-row, compile-time-lane shfl broadcasts (NEW)
//   ssteqr  : register D/E/Z via rget/rset (R9-passing, verbatim)
//   sormtr  : column-owned regs, compile-time-lane shfl broadcasts (NEW)
//   MLP     : unchanged
// Scalar arithmetic order identical to the passing versions.
// ---------------------------------------------------------------------------
__global__ void solve_kernel(const float* __restrict__ W1, const float* __restrict__ b1,
                             const float* __restrict__ W2, const float* __restrict__ b2,
                             float* __restrict__ out) {
    __shared__ float gram[NPAIR];
    __shared__ float Zs[DDIM][DDIM];

    const int tid = threadIdx.x;
    const int wrp = tid >> 5;
    const int lane = tid & 31;
    const int n = DDIM;

    // ---- stage 1: tree-reduce partials (all 8 warps) ----
    for (int k = wrp; k < NPAIR; k += 8) {
        float s = 0.f;
        for (int i = lane; i < GGRID; i += 32) s += g_part[k][i];
#pragma unroll
        for (int off = 16; off > 0; off >>= 1)
            s += __shfl_down_sync(FULLM, s, off);
        if (lane == 0) gram[k] = s;
    }
    __syncthreads();
    if (tid >= 32) return;

    // ---- lane r (<10) owns row r of symmetric A in registers ----
    float Arow[DDIM];
    if (lane < DDIM) {
#pragma unroll
        for (int c = 0; c < DDIM; c++) {
            int lo = (lane < c) ? lane : c;
            int hi = (lane < c) ? c : lane;
            Arow[c] = gram[lo * DDIM - (lo * (lo - 1)) / 2 + (hi - lo)];
        }
    } else {
#pragma unroll
        for (int c = 0; c < DDIM; c++) Arow[c] = 0.f;
    }

    float D[DDIM], E[DDIM], Tau[DDIM - 1];

    // ---------------- ssytd2 (uplo='L'), lane-owns-row ----------------
    // All shfl: full warp, compile-time source lanes, uniform conditions.
#pragma unroll
    for (int i = 0; i < DDIM - 1; i++) {
        // broadcast column i (Householder source): vbc[c] = A[c][i]
        float vbc[DDIM];
#pragma unroll
        for (int c = i + 1; c < DDIM; c++) vbc[c] = __shfl_sync(FULLM, Arow[i], c);
        float alpha = vbc[i + 1];
        float xnorm = 0.f;
#pragma unroll
        for (int r = i + 2; r < DDIM; r++) xnorm += vbc[r] * vbc[r];
        xnorm = fsqrta(xnorm);
        float taui = 0.f, Ei;
        if (xnorm != 0.f) {                      // uniform (inputs uniform)
            float beta = -signf(lapy2f(alpha, xnorm), alpha);
            taui = fdivf(beta - alpha, beta);
            float sc = fdivf(1.f, alpha - beta);
#pragma unroll
            for (int r = i + 2; r < DDIM; r++) vbc[r] *= sc;
            if (lane >= i + 2 && lane < DDIM) Arow[i] *= sc;   // persist v for sormtr
            Ei = beta;
        } else {
            Ei = alpha;
        }
        E[i] = Ei;                               // uniform scalar -> replicated array
        Tau[i] = taui;
        if (taui != 0.f) {                       // uniform
            // per-lane pv_r = taui * (row_r . v), LAPACK summation order
            float s = Arow[i + 1];
#pragma unroll
            for (int c = i + 2; c < DDIM; c++) s += Arow[c] * vbc[c];
            float pvr = taui * s;
            float pvb[DDIM];
#pragma unroll
            for (int r = i + 1; r < DDIM; r++) pvb[r] = __shfl_sync(FULLM, pvr, r);
            float vtp = pvb[i + 1];
#pragma unroll
            for (int r = i + 2; r < DDIM; r++) vtp += pvb[r] * vbc[r];
            float alph = -0.5f * taui * vtp;
            pvb[i + 1] += alph;
#pragma unroll
            for (int r = i + 2; r < DDIM; r++) pvb[r] += alph * vbc[r];
            // rank-2 update: lane r updates its own full symmetric row
            if (lane >= i + 1 && lane < DDIM) {
                float vr = (lane == i + 1) ? 1.f : Arow[i];
                float wr = (lane == i + 1) ? (pvr + alph) : (pvr + alph * Arow[i]);
#pragma unroll
                for (int c = i + 1; c < DDIM; c++) {
                    float vc = (c == i + 1) ? 1.f : vbc[c];
                    Arow[c] -= vr * pvb[c] + wr * vc;
                }
            }
        }
        D[i] = __shfl_sync(FULLM, Arow[i], i);   // A[i][i] (finalized in iter i-1)
    }
    D[DDIM - 1] = __shfl_sync(FULLM, Arow[DDIM - 1], DDIM - 1);
    E[DDIM - 1] = 0.f;

    // lane owns Z row 'lane' in registers
    float Z[DDIM];
#pragma unroll
    for (int k = 0; k < DDIM; k++) Z[k] = (lane == k) ? 1.f : 0.f;

    // ---------------- ssteqr (compz='I'), register-resident (R9 verbatim) --
    {
        const float eps = 5.9604645e-8f;
        const float eps2 = eps * eps;
        const float safmin = 1.17549435e-38f;
        const int nmaxit = n * 30;
        int jtot = 0;
        int l1 = 1;
        while (l1 <= n) {
            if (l1 > 1) rset(E, l1 - 2, 0.f);
            int m = n;
            {
                bool found = false;
#pragma unroll
                for (int mm = 1; mm <= DDIM - 1; mm++) {
                    if (!found && mm >= l1) {
                        float tst = fabsf(E[mm - 1]);
                        if (tst == 0.f) { m = mm; found = true; }
                        else if (tst <= fsqrta(fabsf(D[mm - 1])) * fsqrta(fabsf(D[mm])) * eps) {
                            E[mm - 1] = 0.f; m = mm; found = true;
                        }
                    }
                }
            }
            int l = l1, lend = m;
            l1 = m + 1;
            if (lend == l) continue;
            float anorm = 0.f;
#pragma unroll
            for (int i = 1; i <= DDIM; i++)
                if (i >= l && i <= lend) anorm = fmaxf(anorm, fabsf(D[i - 1]));
#pragma unroll
            for (int i = 1; i <= DDIM - 1; i++)
                if (i >= l && i <= lend - 1) anorm = fmaxf(anorm, fabsf(E[i - 1]));
            if (anorm == 0.f) continue;
            if (fabsf(rget(D, lend - 1)) < fabsf(rget(D, l - 1))) { int t = l; l = lend; lend = t; }

            if (lend > l) {
                // ---- QL iteration ----
                while (true) {
                    int m2 = lend;
                    if (l != lend) {
                        bool found = false;
#pragma unroll
                        for (int mm = 1; mm <= DDIM - 1; mm++) {
                            if (!found && mm >= l && mm <= lend - 1) {
                                float tst = fabsf(E[mm - 1]); tst = tst * tst;
                                if (tst <= (eps2 * fabsf(D[mm - 1])) * fabsf(D[mm]) + safmin) {
                                    m2 = mm; found = true;
                                }
                            }
                        }
                    }
                    if (m2 < lend) rset(E, m2 - 1, 0.f);
                    float p = rget(D, l - 1);
                    if (m2 == l) {
                        l++;
                        if (l <= lend) continue;
                        break;
                    }
                    if (m2 == l + 1) {
                        float rt1, rt2, cc, ss;
                        laev2f(rget(D, l - 1), rget(E, l - 1), rget(D, l), rt1, rt2, cc, ss);
                        zrot(Z, l - 1, l, cc, ss);
                        rset(D, l - 1, rt1); rset(D, l, rt2); rset(E, l - 1, 0.f);
                        l += 2;
                        if (l <= lend) continue;
                        break;
                    }
                    if (jtot == nmaxit) break;
                    jtot++;
                    float g = fdivf(rget(D, l) - p, 2.f * rget(E, l - 1));
                    float r = lapy2f(g, 1.f);
                    g = rget(D, m2 - 1) - p + fdivf(rget(E, l - 1), g + signf(r, g));
                    float s = 1.f, c = 1.f; p = 0.f;
#pragma unroll
                    for (int i = DDIM - 1; i >= 1; i--) {
                        if (i <= m2 - 1 && i >= l) {
                            float f = s * E[i - 1], b = c * E[i - 1];
                            float rr;
                            lartgf(g, f, c, s, rr);
                            if (i != m2 - 1) E[i] = rr;
                            g = D[i] - p;
                            float r2 = (D[i - 1] - g) * s + 2.f * c * b;
                            p = s * r2;
                            D[i] = g + p;
                            g = c * r2 - b;
                            float t1 = Z[i], t0 = Z[i - 1];
                            Z[i]     = c * t1 + s * t0;
                            Z[i - 1] = -s * t1 + c * t0;
                        }
                    }
                    rset(D, l - 1, rget(D, l - 1) - p);
                    rset(E, l - 1, g);
                }
            } else {
                // ---- QR iteration ----
                while (true) {
                    int m2 = lend;
                    if (l != lend) {
                        bool found = false;
#pragma unroll
                        for (int mm = DDIM; mm >= 2; mm--) {
                            if (!found && mm <= l && mm >= lend + 1) {
                                float tst = fabsf(E[mm - 2]); tst = tst * tst;
                                if (tst <= (eps2 * fabsf(D[mm - 1])) * fabsf(D[mm - 2]) + safmin) {
                                    m2 = mm; found = true;
                                }
                            }
                        }
                    }
                    if (m2 > lend) rset(E, m2 - 2, 0.f);
                    float p = rget(D, l - 1);
                    if (m2 == l) {
                        l--;
                        if (l >= lend) continue;
                        break;
                    }
                    if (m2 == l - 1) {
                        float rt1, rt2, cc, ss;
                        laev2f(rget(D, l - 2), rget(E, l - 2), rget(D, l - 1), rt1, rt2, cc, ss);
                        zrot(Z, l - 2, l - 1, cc, ss);
                        rset(D, l - 2, rt1); rset(D, l - 1, rt2); rset(E, l - 2, 0.f);
                        l -= 2;
                        if (l >= lend) continue;
                        break;
                    }
                    if (jtot == nmaxit) break;
                    jtot++;
                    float g = fdivf(rget(D, l - 2) - p, 2.f * rget(E, l - 2));
                    float r = lapy2f(g, 1.f);
                    g = rget(D, m2 - 1) - p + fdivf(rget(E, l - 2), g + signf(r, g));
                    float s = 1.f, c = 1.f; p = 0.f;
#pragma unroll
                    for (int i = 1; i <= DDIM - 1; i++) {
                        if (i >= m2 && i <= l - 1) {
                            float f = s * E[i - 1], b = c * E[i - 1];
                            float rr;
                            lartgf(g, f, c, s, rr);
                            if (i >= 2 && i != m2) E[i - 2] = rr;
                            g = D[i - 1] - p;
                            float r2 = (D[i] - g) * s + 2.f * c * b;
                            p = s * r2;
                            D[i - 1] = g + p;
                            g = c * r2 - b;
                            float t1 = Z[i], t0 = Z[i - 1];
                            Z[i]     = c * t1 - s * t0;
                            Z[i - 1] = s * t1 + c * t0;
                        }
                    }
                    rset(D, l - 1, rget(D, l - 1) - p);
                    rset(E, l - 2, g);
                }
            }
        }

        // selection sort ascending + Z column swaps (R9 verbatim)
#pragma unroll
        for (int ii = 2; ii <= DDIM; ii++) {
            int k = ii - 1;
            float p = D[ii - 2];
#pragma unroll
            for (int j = 2; j <= DDIM; j++) {
                if (j >= ii) {
                    float dj = D[j - 1];
                    if (dj < p) { k = j; p = dj; }
                }
            }
            if (k != ii - 1) {
                rset(D, k - 1, D[ii - 2]);
                D[ii - 2] = p;
                float t = Z[ii - 2];
                Z[ii - 2] = rget(Z, k - 1);
                rset(Z, k - 1, t);
            }
        }
    }

    // ---- transpose Z (row-owned regs -> column-owned regs) via smem ----
    if (lane < n) {
#pragma unroll
        for (int k = 0; k < DDIM; k++) Zs[lane][k] = Z[k];
    }
    __syncwarp();
    float Zc[DDIM];
    if (lane < DDIM) {
#pragma unroll
        for (int r = 0; r < DDIM; r++) Zc[r] = Zs[r][lane];
    } else {
#pragma unroll
        for (int r = 0; r < DDIM; r++) Zc[r] = 0.f;
    }

    // ---------------- sormtr, column-owned; v via compile-time-lane shfl ---
#pragma unroll
    for (int i = DDIM - 2; i >= 0; i--) {
        float vv[DDIM];
#pragma unroll
        for (int r = i + 2; r < DDIM; r++) vv[r] = __shfl_sync(FULLM, Arow[i], r);
        if (Tau[i] != 0.f) {                     // uniform
            float s = Zc[i + 1];
#pragma unroll
            for (int r = i + 2; r < DDIM; r++) s += vv[r] * Zc[r];
            s *= Tau[i];
            Zc[i + 1] -= s;
#pragma unroll
            for (int r = i + 2; r < DDIM; r++) Zc[r] -= s * vv[r];
        }
    }

    // ---- transpose back (column-owned -> row reads) via smem ----
    __syncwarp();
    if (lane < DDIM) {
#pragma unroll
        for (int r = 0; r < DDIM; r++) Zs[r][lane] = Zc[r];
    }
    __syncwarp();

    // ---------------- MLP: relu(w @ W1^T + b1) @ W2^T + b2; 0.5*(sigmoid+1)
    if (lane < DDIM) {
        float zr[DDIM];
#pragma unroll
        for (int k = 0; k < DDIM; k++) zr[k] = Zs[lane][k];
        float y2 = b2[0];
        for (int h = 0; h < HID; h++) {
            float a = b1[h];
#pragma unroll
            for (int k = 0; k < DDIM; k++) a += zr[k] * W1[h * DDIM + k];
            a = fmaxf(a, 0.f);
            y2 += a * W2[h];
        }
        out[lane] = 0.5f * (fdivf(1.f, 1.f + __expf(-y2)) + 1.f);
    }
}

// ---------------------------------------------------------------------------
extern "C" void kernel_launch(void* const* d_in, const int* in_sizes, int n_in,
                              void* d_out, int out_size) {
    const float* x  = (const float*)d_in[0];
    const float* W1 = (const float*)d_in[1];
    const float* b1 = (const float*)d_in[2];
    const float* W2 = (const float*)d_in[3];
    const float* b2 = (const float*)d_in[4];
    long long nrows = (long long)in_sizes[0] / DDIM;

    gram_kernel<<<GGRID, GTPB>>>(x, nrows);
    solve_kernel<<<1, GTPB>>>(W1, b1, W2, b2, (float*)d_out);
}

// round 12
// speedup vs baseline: 1.2355x; 1.0382x over previous
#include <cuda_runtime.h>
#include <cstdint>

#define DDIM 10
#define NPAIR 55
#define GTPB 256
#define GGRID 296            // 148 SMs x 2 blocks -> one full wave
#define ROWS_TILE 512
#define TILE_F4 (ROWS_TILE * DDIM / 4)
#define TILE_FLOATS (ROWS_TILE * DDIM)
#define HID 16
#define FULLM 0xffffffffu

// Deterministic two-stage reduction scratch (no atomics, no allocation).
__device__ float g_part[NPAIR][GGRID];

// ---------------------------------------------------------------------------
// async-copy helpers
// ---------------------------------------------------------------------------
__device__ __forceinline__ void cp_async16(uint32_t smem_dst, const void* gsrc) {
    asm volatile("cp.async.cg.shared.global [%0], [%1], 16;\n"
                 :: "r"(smem_dst), "l"(gsrc));
}
__device__ __forceinline__ void cp_commit() { asm volatile("cp.async.commit_group;\n"); }
__device__ __forceinline__ void cp_wait0() { asm volatile("cp.async.wait_group 0;\n"); }
__device__ __forceinline__ void cp_wait1() { asm volatile("cp.async.wait_group 1;\n"); }

// ---------------------------------------------------------------------------
// Kernel 1: Gram partials. Proven at ~25us — unchanged since R6.
// ---------------------------------------------------------------------------
__global__ void __launch_bounds__(GTPB, 2)
gram_kernel(const float* __restrict__ x, long long nrows) {
    __shared__ __align__(16) float sbuf[2][TILE_FLOATS];
    __shared__ float swarp[GTPB / 32][NPAIR];

    float acc[NPAIR];
#pragma unroll
    for (int k = 0; k < NPAIR; k++) acc[k] = 0.f;

    const long long ntiles = (nrows + ROWS_TILE - 1) / ROWS_TILE;
    const long long totalf4 = nrows * (long long)DDIM / 4;
    const float4* xsrc = reinterpret_cast<const float4*>(x);
    const uint32_t sbase = (uint32_t)__cvta_generic_to_shared(&sbuf[0][0]);

    long long t = blockIdx.x;
    bool havecur = (t < ntiles);

    if (havecur) {
        long long base4 = t * (long long)TILE_F4;
#pragma unroll
        for (int j = 0; j < TILE_F4 / GTPB; j++) {
            int i = threadIdx.x + j * GTPB;
            long long g4 = base4 + i;
            if (g4 < totalf4) {
                cp_async16(sbase + (uint32_t)i * 16u, xsrc + g4);
            } else {
                float4 z = make_float4(0.f, 0.f, 0.f, 0.f);
                reinterpret_cast<float4*>(&sbuf[0][0])[i] = z;
            }
        }
        cp_commit();
    }

    int buf = 0;
    while (havecur) {
        long long tn = t + (long long)GGRID;
        bool havenext = (tn < ntiles);
        if (havenext) {
            long long base4 = tn * (long long)TILE_F4;
            uint32_t dbase = sbase + (uint32_t)(buf ^ 1) * (TILE_FLOATS * 4u);
#pragma unroll
            for (int j = 0; j < TILE_F4 / GTPB; j++) {
                int i = threadIdx.x + j * GTPB;
                long long g4 = base4 + i;
                if (g4 < totalf4) {
                    cp_async16(dbase + (uint32_t)i * 16u, xsrc + g4);
                } else {
                    float4 z = make_float4(0.f, 0.f, 0.f, 0.f);
                    reinterpret_cast<float4*>(&sbuf[buf ^ 1][0])[i] = z;
                }
            }
            cp_commit();
            cp_wait1();
        } else {
            cp_wait0();
        }
        __syncthreads();

        const float* sb = &sbuf[buf][0];
#pragma unroll
        for (int half = 0; half < 2; half++) {
            int r0 = threadIdx.x + half * GTPB;
            long long row_g = t * (long long)ROWS_TILE + r0;
            if (row_g < nrows) {
                float r[DDIM];
                const float2* rp = reinterpret_cast<const float2*>(sb + r0 * DDIM);
#pragma unroll
                for (int j = 0; j < 5; j++) {
                    float2 v = rp[j];
                    r[2 * j] = v.x;
                    r[2 * j + 1] = v.y;
                }
                int k = 0;
#pragma unroll
                for (int i = 0; i < DDIM; i++)
#pragma unroll
                    for (int j = i; j < DDIM; j++) acc[k++] += r[i] * r[j];
            }
        }
        __syncthreads();

        t = tn;
        havecur = havenext;
        buf ^= 1;
    }

#pragma unroll
    for (int k = 0; k < NPAIR; k++) {
#pragma unroll
        for (int off = 16; off > 0; off >>= 1)
            acc[k] += __shfl_down_sync(FULLM, acc[k], off);
    }
    int wid = threadIdx.x >> 5, lane = threadIdx.x & 31;
    if (lane == 0) {
#pragma unroll
        for (int k = 0; k < NPAIR; k++) swarp[wid][k] = acc[k];
    }
    __syncthreads();
    if (threadIdx.x < NPAIR) {
        float s = 0.f;
#pragma unroll
        for (int w = 0; w < GTPB / 32; w++) s += swarp[w][threadIdx.x];
        g_part[threadIdx.x][blockIdx.x] = s;
    }
}

// ---------------------------------------------------------------------------
// Fast-approx scalar helpers (sign-safe)
// ---------------------------------------------------------------------------
__device__ __forceinline__ float fdivf(float a, float b) { return __fdividef(a, b); }
__device__ __forceinline__ float fsqrta(float x) {
    float r;
    asm("sqrt.approx.f32 %0, %1;" : "=f"(r) : "f"(x));
    return r;
}

// register-array dynamic-index helpers (SEL chains; steqr/sort only)
__device__ __forceinline__ float rget(const float a[DDIM], int i) {
    float v = a[0];
#pragma unroll
    for (int k = 1; k < DDIM; k++) if (k == i) v = a[k];
    return v;
}
__device__ __forceinline__ void rset(float a[DDIM], int i, float v) {
#pragma unroll
    for (int k = 0; k < DDIM; k++) if (k == i) a[k] = v;
}
__device__ __forceinline__ void zrot(float Z[DDIM], int c0, int c1, float cc, float ss) {
    float t1 = rget(Z, c1), t0 = rget(Z, c0);
    rset(Z, c1, cc * t1 - ss * t0);
    rset(Z, c0, ss * t1 + cc * t0);
}

// ---------------------------------------------------------------------------
// LAPACK-faithful helpers. R12 change: shorter critical paths, SAME signs.
// ---------------------------------------------------------------------------
// lapy2: operands here are <= ~1e7, so x^2+y^2 <= ~2e14 — no overflow risk;
// direct fused form replaces the scaled div+sqrt chain. Magnitude-only change.
__device__ __forceinline__ float lapy2f(float x, float y) {
    return fsqrta(__fmaf_rn(x, x, y * y));
}
__device__ __forceinline__ float signf(float a, float b) {
    return (b >= 0.f) ? fabsf(a) : -fabsf(a);
}
// LAPACK >= 3.10 slartg convention: c >= 0, r = sign(d, f), sign(s) = sign(g*f).
// R12: single-rsqrt form. d = t*rd, c = |f|*rd (>=0), s = g*copysign(rd, f)
// == g/r up to approx rounding. All sign decisions identical to the div form.
__device__ __forceinline__ void lartgf(float f, float g, float& c, float& s, float& r) {
    if (g == 0.f) { c = 1.f; s = 0.f; r = f; }
    else if (f == 0.f) { c = 0.f; s = (g > 0.f) ? 1.f : -1.f; r = fabsf(g); }
    else {
        float t = __fmaf_rn(f, f, g * g);
        float rd = rsqrtf(t);
        float d = t * rd;                  // ~sqrt(t) > 0
        c = fabsf(f) * rd;
        r = signf(d, f);
        s = g * copysignf(rd, f);          // == g / r (approx), same sign
    }
}
// LAPACK slaev2 (exact sign logic preserved; divisions already approx)
__device__ void laev2f(float a, float b, float c_, float& rt1, float& rt2,
                       float& cs1, float& sn1) {
    float sm = a + c_;
    float df = a - c_;
    float adf = fabsf(df);
    float tb = b + b;
    float ab = fabsf(tb);
    float acmx, acmn;
    if (fabsf(a) > fabsf(c_)) { acmx = a; acmn = c_; } else { acmx = c_; acmn = a; }
    float rt;
    if (adf > ab)      { float q = fdivf(ab, adf); rt = adf * fsqrta(1.f + q * q); }
    else if (adf < ab) { float q = fdivf(adf, ab); rt = ab * fsqrta(1.f + q * q); }
    else               { rt = ab * fsqrta(2.f); }
    int sgn1;
    if (sm < 0.f) {
        rt1 = 0.5f * (sm - rt); sgn1 = -1;
        rt2 = fdivf(acmx, rt1) * acmn - fdivf(b, rt1) * b;
    } else if (sm > 0.f) {
        rt1 = 0.5f * (sm + rt); sgn1 = 1;
        rt2 = fdivf(acmx, rt1) * acmn - fdivf(b, rt1) * b;
    } else {
        rt1 = 0.5f * rt; rt2 = -0.5f * rt; sgn1 = 1;
    }
    float cs; int sgn2;
    if (df >= 0.f) { cs = df + rt; sgn2 = 1; }
    else           { cs = df - rt; sgn2 = -1; }
    float acs = fabsf(cs);
    if (acs > ab) {
        float ct = -fdivf(tb, cs);
        sn1 = rsqrtf(1.f + ct * ct);
        cs1 = ct * sn1;
    } else {
        if (ab == 0.f) { cs1 = 1.f; sn1 = 0.f; }
        else {
            float tn = -fdivf(cs, tb);
            cs1 = rsqrtf(1.f + tn * tn);
            sn1 = tn * cs1;
        }
    }
    if (sgn1 == sgn2) { float tn = cs1; cs1 = -sn1; sn1 = tn; }
}

// ---------------------------------------------------------------------------
// Kernel 2 (R11-passing structure, helpers above are the only change):
//   8-warp partial reduce; warp 0: lane-owns-row ssytd2 (shfl),
//   register steqr (rget/rset), column-owned sormtr (shfl), MLP.
// ---------------------------------------------------------------------------
__global__ void solve_kernel(const float* __restrict__ W1, const float* __restrict__ b1,
                             const float* __restrict__ W2, const float* __restrict__ b2,
                             float* __restrict__ out) {
    __shared__ float gram[NPAIR];
    __shared__ float Zs[DDIM][DDIM];

    const int tid = threadIdx.x;
    const int wrp = tid >> 5;
    const int lane = tid & 31;
    const int n = DDIM;

    // ---- stage 1: tree-reduce partials (all 8 warps) ----
    for (int k = wrp; k < NPAIR; k += 8) {
        float s = 0.f;
        for (int i = lane; i < GGRID; i += 32) s += g_part[k][i];
#pragma unroll
        for (int off = 16; off > 0; off >>= 1)
            s += __shfl_down_sync(FULLM, s, off);
        if (lane == 0) gram[k] = s;
    }
    __syncthreads();
    if (tid >= 32) return;

    // ---- lane r (<10) owns row r of symmetric A in registers ----
    float Arow[DDIM];
    if (lane < DDIM) {
#pragma unroll
        for (int c = 0; c < DDIM; c++) {
            int lo = (lane < c) ? lane : c;
            int hi = (lane < c) ? c : lane;
            Arow[c] = gram[lo * DDIM - (lo * (lo - 1)) / 2 + (hi - lo)];
        }
    } else {
#pragma unroll
        for (int c = 0; c < DDIM; c++) Arow[c] = 0.f;
    }

    float D[DDIM], E[DDIM], Tau[DDIM - 1];

    // ---------------- ssytd2 (uplo='L'), lane-owns-row ----------------
#pragma unroll
    for (int i = 0; i < DDIM - 1; i++) {
        float vbc[DDIM];
#pragma unroll
        for (int c = i + 1; c < DDIM; c++) vbc[c] = __shfl_sync(FULLM, Arow[i], c);
        float alpha = vbc[i + 1];
        float xnorm = 0.f;
#pragma unroll
        for (int r = i + 2; r < DDIM; r++) xnorm += vbc[r] * vbc[r];
        xnorm = fsqrta(xnorm);
        float taui = 0.f, Ei;
        if (xnorm != 0.f) {
            float beta = -signf(lapy2f(alpha, xnorm), alpha);
            taui = fdivf(beta - alpha, beta);
            float sc = fdivf(1.f, alpha - beta);
#pragma unroll
            for (int r = i + 2; r < DDIM; r++) vbc[r] *= sc;
            if (lane >= i + 2 && lane < DDIM) Arow[i] *= sc;   // persist v for sormtr
            Ei = beta;
        } else {
            Ei = alpha;
        }
        E[i] = Ei;
        Tau[i] = taui;
        if (taui != 0.f) {
            float s = Arow[i + 1];
#pragma unroll
            for (int c = i + 2; c < DDIM; c++) s += Arow[c] * vbc[c];
            float pvr = taui * s;
            float pvb[DDIM];
#pragma unroll
            for (int r = i + 1; r < DDIM; r++) pvb[r] = __shfl_sync(FULLM, pvr, r);
            float vtp = pvb[i + 1];
#pragma unroll
            for (int r = i + 2; r < DDIM; r++) vtp += pvb[r] * vbc[r];
            float alph = -0.5f * taui * vtp;
            pvb[i + 1] += alph;
#pragma unroll
            for (int r = i + 2; r < DDIM; r++) pvb[r] += alph * vbc[r];
            if (lane >= i + 1 && lane < DDIM) {
                float vr = (lane == i + 1) ? 1.f : Arow[i];
                float wr = (lane == i + 1) ? (pvr + alph) : (pvr + alph * Arow[i]);
#pragma unroll
                for (int c = i + 1; c < DDIM; c++) {
                    float vc = (c == i + 1) ? 1.f : vbc[c];
                    Arow[c] -= vr * pvb[c] + wr * vc;
                }
            }
        }
        D[i] = __shfl_sync(FULLM, Arow[i], i);
    }
    D[DDIM - 1] = __shfl_sync(FULLM, Arow[DDIM - 1], DDIM - 1);
    E[DDIM - 1] = 0.f;

    // lane owns Z row 'lane' in registers
    float Z[DDIM];
#pragma unroll
    for (int k = 0; k < DDIM; k++) Z[k] = (lane == k) ? 1.f : 0.f;

    // ---------------- ssteqr (compz='I'), register-resident ----------------
    {
        const float eps = 5.9604645e-8f;
        const float eps2 = eps * eps;
        const float safmin = 1.17549435e-38f;
        const int nmaxit = n * 30;
        int jtot = 0;
        int l1 = 1;
        while (l1 <= n) {
            if (l1 > 1) rset(E, l1 - 2, 0.f);
            int m = n;
            {
                bool found = false;
#pragma unroll
                for (int mm = 1; mm <= DDIM - 1; mm++) {
                    if (!found && mm >= l1) {
                        float tst = fabsf(E[mm - 1]);
                        if (tst == 0.f) { m = mm; found = true; }
                        else if (tst <= fsqrta(fabsf(D[mm - 1])) * fsqrta(fabsf(D[mm])) * eps) {
                            E[mm - 1] = 0.f; m = mm; found = true;
                        }
                    }
                }
            }
            int l = l1, lend = m;
            l1 = m + 1;
            if (lend == l) continue;
            float anorm = 0.f;
#pragma unroll
            for (int i = 1; i <= DDIM; i++)
                if (i >= l && i <= lend) anorm = fmaxf(anorm, fabsf(D[i - 1]));
#pragma unroll
            for (int i = 1; i <= DDIM - 1; i++)
                if (i >= l && i <= lend - 1) anorm = fmaxf(anorm, fabsf(E[i - 1]));
            if (anorm == 0.f) continue;
            if (fabsf(rget(D, lend - 1)) < fabsf(rget(D, l - 1))) { int t = l; l = lend; lend = t; }

            if (lend > l) {
                // ---- QL iteration ----
                while (true) {
                    int m2 = lend;
                    if (l != lend) {
                        bool found = false;
#pragma unroll
                        for (int mm = 1; mm <= DDIM - 1; mm++) {
                            if (!found && mm >= l && mm <= lend - 1) {
                                float tst = fabsf(E[mm - 1]); tst = tst * tst;
                                if (tst <= (eps2 * fabsf(D[mm - 1])) * fabsf(D[mm]) + safmin) {
                                    m2 = mm; found = true;
                                }
                            }
                        }
                    }
                    if (m2 < lend) rset(E, m2 - 1, 0.f);
                    float p = rget(D, l - 1);
                    if (m2 == l) {
                        l++;
                        if (l <= lend) continue;
                        break;
                    }
                    if (m2 == l + 1) {
                        float rt1, rt2, cc, ss;
                        laev2f(rget(D, l - 1), rget(E, l - 1), rget(D, l), rt1, rt2, cc, ss);
                        zrot(Z, l - 1, l, cc, ss);
                        rset(D, l - 1, rt1); rset(D, l, rt2); rset(E, l - 1, 0.f);
                        l += 2;
                        if (l <= lend) continue;
                        break;
                    }
                    if (jtot == nmaxit) break;
                    jtot++;
                    float g = fdivf(rget(D, l) - p, 2.f * rget(E, l - 1));
                    float r = lapy2f(g, 1.f);
                    g = rget(D, m2 - 1) - p + fdivf(rget(E, l - 1), g + signf(r, g));
                    float s = 1.f, c = 1.f; p = 0.f;
#pragma unroll
                    for (int i = DDIM - 1; i >= 1; i--) {
                        if (i <= m2 - 1 && i >= l) {
                            float f = s * E[i - 1], b = c * E[i - 1];
                            float rr;
                            lartgf(g, f, c, s, rr);
                            if (i != m2 - 1) E[i] = rr;
                            g = D[i] - p;
                            float r2 = (D[i - 1] - g) * s + 2.f * c * b;
                            p = s * r2;
                            D[i] = g + p;
                            g = c * r2 - b;
                            float t1 = Z[i], t0 = Z[i - 1];
                            Z[i]     = c * t1 + s * t0;
                            Z[i - 1] = -s * t1 + c * t0;
                        }
                    }
                    rset(D, l - 1, rget(D, l - 1) - p);
                    rset(E, l - 1, g);
                }
            } else {
                // ---- QR iteration ----
                while (true) {
                    int m2 = lend;
                    if (l != lend) {
                        bool found = false;
#pragma unroll
                        for (int mm = DDIM; mm >= 2; mm--) {
                            if (!found && mm <= l && mm >= lend + 1) {
                                float tst = fabsf(E[mm - 2]); tst = tst * tst;
                                if (tst <= (eps2 * fabsf(D[mm - 1])) * fabsf(D[mm - 2]) + safmin) {
                                    m2 = mm; found = true;
                                }
                            }
                        }
                    }
                    if (m2 > lend) rset(E, m2 - 2, 0.f);
                    float p = rget(D, l - 1);
                    if (m2 == l) {
                        l--;
                        if (l >= lend) continue;
                        break;
                    }
                    if (m2 == l - 1) {
                        float rt1, rt2, cc, ss;
                        laev2f(rget(D, l - 2), rget(E, l - 2), rget(D, l - 1), rt1, rt2, cc, ss);
                        zrot(Z, l - 2, l - 1, cc, ss);
                        rset(D, l - 2, rt1); rset(D, l - 1, rt2); rset(E, l - 2, 0.f);
                        l -= 2;
                        if (l >= lend) continue;
                        break;
                    }
                    if (jtot == nmaxit) break;
                    jtot++;
                    float g = fdivf(rget(D, l - 2) - p, 2.f * rget(E, l - 2));
                    float r = lapy2f(g, 1.f);
                    g = rget(D, m2 - 1) - p + fdivf(rget(E, l - 2), g + signf(r, g));
                    float s = 1.f, c = 1.f; p = 0.f;
#pragma unroll
                    for (int i = 1; i <= DDIM - 1; i++) {
                        if (i >= m2 && i <= l - 1) {
                            float f = s * E[i - 1], b = c * E[i - 1];
                            float rr;
                            lartgf(g, f, c, s, rr);
                            if (i >= 2 && i != m2) E[i - 2] = rr;
                            g = D[i - 1] - p;
                            float r2 = (D[i] - g) * s + 2.f * c * b;
                            p = s * r2;
                            D[i - 1] = g + p;
                            g = c * r2 - b;
                            float t1 = Z[i], t0 = Z[i - 1];
                            Z[i]     = c * t1 - s * t0;
                            Z[i - 1] = s * t1 + c * t0;
                        }
                    }
                    rset(D, l - 1, rget(D, l - 1) - p);
                    rset(E, l - 2, g);
                }
            }
        }

        // selection sort ascending + Z column swaps
#pragma unroll
        for (int ii = 2; ii <= DDIM; ii++) {
            int k = ii - 1;
            float p = D[ii - 2];
#pragma unroll
            for (int j = 2; j <= DDIM; j++) {
                if (j >= ii) {
                    float dj = D[j - 1];
                    if (dj < p) { k = j; p = dj; }
                }
            }
            if (k != ii - 1) {
                rset(D, k - 1, D[ii - 2]);
                D[ii - 2] = p;
                float t = Z[ii - 2];
                Z[ii - 2] = rget(Z, k - 1);
                rset(Z, k - 1, t);
            }
        }
    }

    // ---- transpose Z (row-owned regs -> column-owned regs) via smem ----
    if (lane < n) {
#pragma unroll
        for (int k = 0; k < DDIM; k++) Zs[lane][k] = Z[k];
    }
    __syncwarp();
    float Zc[DDIM];
    if (lane < DDIM) {
#pragma unroll
        for (int r = 0; r < DDIM; r++) Zc[r] = Zs[r][lane];
    } else {
#pragma unroll
        for (int r = 0; r < DDIM; r++) Zc[r] = 0.f;
    }

    // ---------------- sormtr, column-owned; v via compile-time-lane shfl ---
#pragma unroll
    for (int i = DDIM - 2; i >= 0; i--) {
        float vv[DDIM];
#pragma unroll
        for (int r = i + 2; r < DDIM; r++) vv[r] = __shfl_sync(FULLM, Arow[i], r);
        if (Tau[i] != 0.f) {
            float s = Zc[i + 1];
#pragma unroll
            for (int r = i + 2; r < DDIM; r++) s += vv[r] * Zc[r];
            s *= Tau[i];
            Zc[i + 1] -= s;
#pragma unroll
            for (int r = i + 2; r < DDIM; r++) Zc[r] -= s * vv[r];
        }
    }

    // ---- transpose back (column-owned -> row reads) via smem ----
    __syncwarp();
    if (lane < DDIM) {
#pragma unroll
        for (int r = 0; r < DDIM; r++) Zs[r][lane] = Zc[r];
    }
    __syncwarp();

    // ---------------- MLP: relu(w @ W1^T + b1) @ W2^T + b2; 0.5*(sigmoid+1)
    if (lane < DDIM) {
        float zr[DDIM];
#pragma unroll
        for (int k = 0; k < DDIM; k++) zr[k] = Zs[lane][k];
        float y2 = b2[0];
        for (int h = 0; h < HID; h++) {
            float a = b1[h];
#pragma unroll
            for (int k = 0; k < DDIM; k++) a += zr[k] * W1[h * DDIM + k];
            a = fmaxf(a, 0.f);
            y2 += a * W2[h];
        }
        out[lane] = 0.5f * (fdivf(1.f, 1.f + __expf(-y2)) + 1.f);
    }
}

// ---------------------------------------------------------------------------
extern "C" void kernel_launch(void* const* d_in, const int* in_sizes, int n_in,
                              void* d_out, int out_size) {
    const float* x  = (const float*)d_in[0];
    const float* W1 = (const float*)d_in[1];
    const float* b1 = (const float*)d_in[2];
    const float* W2 = (const float*)d_in[3];
    const float* b2 = (const float*)d_in[4];
    long long nrows = (long long)in_sizes[0] / DDIM;

    gram_kernel<<<GGRID, GTPB>>>(x, nrows);
    solve_kernel<<<1, GTPB>>>(W1, b1, W2, b2, (float*)d_out);
}

// round 13
// speedup vs baseline: 1.2558x; 1.0164x over previous
#include <cuda_runtime.h>
#include <cstdint>

#define DDIM 10
#define NPAIR 55
#define GTPB 256
#define GGRID 296            // 148 SMs x 2 blocks -> one full wave
#define ROWS_TILE 512
#define TILE_F4 (ROWS_TILE * DDIM / 4)
#define TILE_FLOATS (ROWS_TILE * DDIM)
#define HID 16
#define FULLM 0xffffffffu
#define SOLVE_GRID 148       // issue-throttle workaround: body>32KB @grid>=148

// Deterministic two-stage reduction scratch (no atomics, no allocation).
__device__ float g_part[NPAIR][GGRID];

// ---------------------------------------------------------------------------
// async-copy helpers
// ---------------------------------------------------------------------------
__device__ __forceinline__ void cp_async16(uint32_t smem_dst, const void* gsrc) {
    asm volatile("cp.async.cg.shared.global [%0], [%1], 16;\n"
                 :: "r"(smem_dst), "l"(gsrc));
}
__device__ __forceinline__ void cp_commit() { asm volatile("cp.async.commit_group;\n"); }
__device__ __forceinline__ void cp_wait0() { asm volatile("cp.async.wait_group 0;\n"); }
__device__ __forceinline__ void cp_wait1() { asm volatile("cp.async.wait_group 1;\n"); }

// ---------------------------------------------------------------------------
// Kernel 1: Gram partials. Proven — unchanged since R6.
// ---------------------------------------------------------------------------
__global__ void __launch_bounds__(GTPB, 2)
gram_kernel(const float* __restrict__ x, long long nrows) {
    __shared__ __align__(16) float sbuf[2][TILE_FLOATS];
    __shared__ float swarp[GTPB / 32][NPAIR];

    float acc[NPAIR];
#pragma unroll
    for (int k = 0; k < NPAIR; k++) acc[k] = 0.f;

    const long long ntiles = (nrows + ROWS_TILE - 1) / ROWS_TILE;
    const long long totalf4 = nrows * (long long)DDIM / 4;
    const float4* xsrc = reinterpret_cast<const float4*>(x);
    const uint32_t sbase = (uint32_t)__cvta_generic_to_shared(&sbuf[0][0]);

    long long t = blockIdx.x;
    bool havecur = (t < ntiles);

    if (havecur) {
        long long base4 = t * (long long)TILE_F4;
#pragma unroll
        for (int j = 0; j < TILE_F4 / GTPB; j++) {
            int i = threadIdx.x + j * GTPB;
            long long g4 = base4 + i;
            if (g4 < totalf4) {
                cp_async16(sbase + (uint32_t)i * 16u, xsrc + g4);
            } else {
                float4 z = make_float4(0.f, 0.f, 0.f, 0.f);
                reinterpret_cast<float4*>(&sbuf[0][0])[i] = z;
            }
        }
        cp_commit();
    }

    int buf = 0;
    while (havecur) {
        long long tn = t + (long long)GGRID;
        bool havenext = (tn < ntiles);
        if (havenext) {
            long long base4 = tn * (long long)TILE_F4;
            uint32_t dbase = sbase + (uint32_t)(buf ^ 1) * (TILE_FLOATS * 4u);
#pragma unroll
            for (int j = 0; j < TILE_F4 / GTPB; j++) {
                int i = threadIdx.x + j * GTPB;
                long long g4 = base4 + i;
                if (g4 < totalf4) {
                    cp_async16(dbase + (uint32_t)i * 16u, xsrc + g4);
                } else {
                    float4 z = make_float4(0.f, 0.f, 0.f, 0.f);
                    reinterpret_cast<float4*>(&sbuf[buf ^ 1][0])[i] = z;
                }
            }
            cp_commit();
            cp_wait1();
        } else {
            cp_wait0();
        }
        __syncthreads();

        const float* sb = &sbuf[buf][0];
#pragma unroll
        for (int half = 0; half < 2; half++) {
            int r0 = threadIdx.x + half * GTPB;
            long long row_g = t * (long long)ROWS_TILE + r0;
            if (row_g < nrows) {
                float r[DDIM];
                const float2* rp = reinterpret_cast<const float2*>(sb + r0 * DDIM);
#pragma unroll
                for (int j = 0; j < 5; j++) {
                    float2 v = rp[j];
                    r[2 * j] = v.x;
                    r[2 * j + 1] = v.y;
                }
                int k = 0;
#pragma unroll
                for (int i = 0; i < DDIM; i++)
#pragma unroll
                    for (int j = i; j < DDIM; j++) acc[k++] += r[i] * r[j];
            }
        }
        __syncthreads();

        t = tn;
        havecur = havenext;
        buf ^= 1;
    }

#pragma unroll
    for (int k = 0; k < NPAIR; k++) {
#pragma unroll
        for (int off = 16; off > 0; off >>= 1)
            acc[k] += __shfl_down_sync(FULLM, acc[k], off);
    }
    int wid = threadIdx.x >> 5, lane = threadIdx.x & 31;
    if (lane == 0) {
#pragma unroll
        for (int k = 0; k < NPAIR; k++) swarp[wid][k] = acc[k];
    }
    __syncthreads();
    if (threadIdx.x < NPAIR) {
        float s = 0.f;
#pragma unroll
        for (int w = 0; w < GTPB / 32; w++) s += swarp[w][threadIdx.x];
        g_part[threadIdx.x][blockIdx.x] = s;
    }
}

// ---------------------------------------------------------------------------
// Fast-approx scalar helpers (sign-safe)
// ---------------------------------------------------------------------------
__device__ __forceinline__ float fdivf(float a, float b) { return __fdividef(a, b); }
__device__ __forceinline__ float fsqrta(float x) {
    float r;
    asm("sqrt.approx.f32 %0, %1;" : "=f"(r) : "f"(x));
    return r;
}

// register-array dynamic-index helpers (SEL chains; steqr only)
__device__ __forceinline__ float rget(const float a[DDIM], int i) {
    float v = a[0];
#pragma unroll
    for (int k = 1; k < DDIM; k++) if (k == i) v = a[k];
    return v;
}
__device__ __forceinline__ void rset(float a[DDIM], int i, float v) {
#pragma unroll
    for (int k = 0; k < DDIM; k++) if (k == i) a[k] = v;
}
__device__ __forceinline__ void zrot(float Z[DDIM], int c0, int c1, float cc, float ss) {
    float t1 = rget(Z, c1), t0 = rget(Z, c0);
    rset(Z, c1, cc * t1 - ss * t0);
    rset(Z, c0, ss * t1 + cc * t0);
}

// ---------------------------------------------------------------------------
// LAPACK-faithful helpers (R12-proven short-chain forms; signs preserved)
// ---------------------------------------------------------------------------
__device__ __forceinline__ float lapy2f(float x, float y) {
    return fsqrta(__fmaf_rn(x, x, y * y));
}
__device__ __forceinline__ float signf(float a, float b) {
    return (b >= 0.f) ? fabsf(a) : -fabsf(a);
}
// LAPACK >= 3.10 slartg convention: c >= 0, r = sign(d, f), sign(s) = sign(g*f).
__device__ __forceinline__ void lartgf(float f, float g, float& c, float& s, float& r) {
    if (g == 0.f) { c = 1.f; s = 0.f; r = f; }
    else if (f == 0.f) { c = 0.f; s = (g > 0.f) ? 1.f : -1.f; r = fabsf(g); }
    else {
        float t = __fmaf_rn(f, f, g * g);
        float rd = rsqrtf(t);
        float d = t * rd;
        c = fabsf(f) * rd;
        r = signf(d, f);
        s = g * copysignf(rd, f);
    }
}
// LAPACK slaev2 (exact sign logic preserved)
__device__ void laev2f(float a, float b, float c_, float& rt1, float& rt2,
                       float& cs1, float& sn1) {
    float sm = a + c_;
    float df = a - c_;
    float adf = fabsf(df);
    float tb = b + b;
    float ab = fabsf(tb);
    float acmx, acmn;
    if (fabsf(a) > fabsf(c_)) { acmx = a; acmn = c_; } else { acmx = c_; acmn = a; }
    float rt;
    if (adf > ab)      { float q = fdivf(ab, adf); rt = adf * fsqrta(1.f + q * q); }
    else if (adf < ab) { float q = fdivf(adf, ab); rt = ab * fsqrta(1.f + q * q); }
    else               { rt = ab * fsqrta(2.f); }
    int sgn1;
    if (sm < 0.f) {
        rt1 = 0.5f * (sm - rt); sgn1 = -1;
        rt2 = fdivf(acmx, rt1) * acmn - fdivf(b, rt1) * b;
    } else if (sm > 0.f) {
        rt1 = 0.5f * (sm + rt); sgn1 = 1;
        rt2 = fdivf(acmx, rt1) * acmn - fdivf(b, rt1) * b;
    } else {
        rt1 = 0.5f * rt; rt2 = -0.5f * rt; sgn1 = 1;
    }
    float cs; int sgn2;
    if (df >= 0.f) { cs = df + rt; sgn2 = 1; }
    else           { cs = df - rt; sgn2 = -1; }
    float acs = fabsf(cs);
    if (acs > ab) {
        float ct = -fdivf(tb, cs);
        sn1 = rsqrtf(1.f + ct * ct);
        cs1 = ct * sn1;
    } else {
        if (ab == 0.f) { cs1 = 1.f; sn1 = 0.f; }
        else {
            float tn = -fdivf(cs, tb);
            cs1 = rsqrtf(1.f + tn * tn);
            sn1 = tn * cs1;
        }
    }
    if (sgn1 == sgn2) { float tn = cs1; cs1 = -sn1; sn1 = tn; }
}

// ---------------------------------------------------------------------------
// Kernel 2 (R12-passing structure). R13 deltas:
//   * grid=SOLVE_GRID; blocks != 0 exit immediately (issue-throttle bypass)
//   * selection sort replaced by stable-rank permutation folded into the
//     Z transpose (semantics-identical for distinct eigenvalues; LAPACK
//     selection sort is stable, so the stable rank reproduces it on ties)
// ---------------------------------------------------------------------------
__global__ void solve_kernel(const float* __restrict__ W1, const float* __restrict__ b1,
                             const float* __restrict__ W2, const float* __restrict__ b2,
                             float* __restrict__ out) {
    if (blockIdx.x != 0) return;        // throttle-bypass ballast blocks

    __shared__ float gram[NPAIR];
    __shared__ float Zs[DDIM][DDIM];

    const int tid = threadIdx.x;
    const int wrp = tid >> 5;
    const int lane = tid & 31;
    const int n = DDIM;

    // ---- stage 1: tree-reduce partials (all 8 warps) ----
    for (int k = wrp; k < NPAIR; k += 8) {
        float s = 0.f;
        for (int i = lane; i < GGRID; i += 32) s += g_part[k][i];
#pragma unroll
        for (int off = 16; off > 0; off >>= 1)
            s += __shfl_down_sync(FULLM, s, off);
        if (lane == 0) gram[k] = s;
    }
    __syncthreads();
    if (tid >= 32) return;

    // ---- lane r (<10) owns row r of symmetric A in registers ----
    float Arow[DDIM];
    if (lane < DDIM) {
#pragma unroll
        for (int c = 0; c < DDIM; c++) {
            int lo = (lane < c) ? lane : c;
            int hi = (lane < c) ? c : lane;
            Arow[c] = gram[lo * DDIM - (lo * (lo - 1)) / 2 + (hi - lo)];
        }
    } else {
#pragma unroll
        for (int c = 0; c < DDIM; c++) Arow[c] = 0.f;
    }

    float D[DDIM], E[DDIM], Tau[DDIM - 1];

    // ---------------- ssytd2 (uplo='L'), lane-owns-row ----------------
#pragma unroll
    for (int i = 0; i < DDIM - 1; i++) {
        float vbc[DDIM];
#pragma unroll
        for (int c = i + 1; c < DDIM; c++) vbc[c] = __shfl_sync(FULLM, Arow[i], c);
        float alpha = vbc[i + 1];
        float xnorm = 0.f;
#pragma unroll
        for (int r = i + 2; r < DDIM; r++) xnorm += vbc[r] * vbc[r];
        xnorm = fsqrta(xnorm);
        float taui = 0.f, Ei;
        if (xnorm != 0.f) {
            float beta = -signf(lapy2f(alpha, xnorm), alpha);
            taui = fdivf(beta - alpha, beta);
            float sc = fdivf(1.f, alpha - beta);
#pragma unroll
            for (int r = i + 2; r < DDIM; r++) vbc[r] *= sc;
            if (lane >= i + 2 && lane < DDIM) Arow[i] *= sc;   // persist v for sormtr
            Ei = beta;
        } else {
            Ei = alpha;
        }
        E[i] = Ei;
        Tau[i] = taui;
        if (taui != 0.f) {
            float s = Arow[i + 1];
#pragma unroll
            for (int c = i + 2; c < DDIM; c++) s += Arow[c] * vbc[c];
            float pvr = taui * s;
            float pvb[DDIM];
#pragma unroll
            for (int r = i + 1; r < DDIM; r++) pvb[r] = __shfl_sync(FULLM, pvr, r);
            float vtp = pvb[i + 1];
#pragma unroll
            for (int r = i + 2; r < DDIM; r++) vtp += pvb[r] * vbc[r];
            float alph = -0.5f * taui * vtp;
            pvb[i + 1] += alph;
#pragma unroll
            for (int r = i + 2; r < DDIM; r++) pvb[r] += alph * vbc[r];
            if (lane >= i + 1 && lane < DDIM) {
                float vr = (lane == i + 1) ? 1.f : Arow[i];
                float wr = (lane == i + 1) ? (pvr + alph) : (pvr + alph * Arow[i]);
#pragma unroll
                for (int c = i + 1; c < DDIM; c++) {
                    float vc = (c == i + 1) ? 1.f : vbc[c];
                    Arow[c] -= vr * pvb[c] + wr * vc;
                }
            }
        }
        D[i] = __shfl_sync(FULLM, Arow[i], i);
    }
    D[DDIM - 1] = __shfl_sync(FULLM, Arow[DDIM - 1], DDIM - 1);
    E[DDIM - 1] = 0.f;

    // lane owns Z row 'lane' in registers
    float Z[DDIM];
#pragma unroll
    for (int k = 0; k < DDIM; k++) Z[k] = (lane == k) ? 1.f : 0.f;

    // ---------------- ssteqr (compz='I'), register-resident ----------------
    {
        const float eps = 5.9604645e-8f;
        const float eps2 = eps * eps;
        const float safmin = 1.17549435e-38f;
        const int nmaxit = n * 30;
        int jtot = 0;
        int l1 = 1;
        while (l1 <= n) {
            if (l1 > 1) rset(E, l1 - 2, 0.f);
            int m = n;
            {
                bool found = false;
#pragma unroll
                for (int mm = 1; mm <= DDIM - 1; mm++) {
                    if (!found && mm >= l1) {
                        float tst = fabsf(E[mm - 1]);
                        if (tst == 0.f) { m = mm; found = true; }
                        else if (tst <= fsqrta(fabsf(D[mm - 1])) * fsqrta(fabsf(D[mm])) * eps) {
                            E[mm - 1] = 0.f; m = mm; found = true;
                        }
                    }
                }
            }
            int l = l1, lend = m;
            l1 = m + 1;
            if (lend == l) continue;
            float anorm = 0.f;
#pragma unroll
            for (int i = 1; i <= DDIM; i++)
                if (i >= l && i <= lend) anorm = fmaxf(anorm, fabsf(D[i - 1]));
#pragma unroll
            for (int i = 1; i <= DDIM - 1; i++)
                if (i >= l && i <= lend - 1) anorm = fmaxf(anorm, fabsf(E[i - 1]));
            if (anorm == 0.f) continue;
            if (fabsf(rget(D, lend - 1)) < fabsf(rget(D, l - 1))) { int t = l; l = lend; lend = t; }

            if (lend > l) {
                // ---- QL iteration ----
                while (true) {
                    int m2 = lend;
                    if (l != lend) {
                        bool found = false;
#pragma unroll
                        for (int mm = 1; mm <= DDIM - 1; mm++) {
                            if (!found && mm >= l && mm <= lend - 1) {
                                float tst = fabsf(E[mm - 1]); tst = tst * tst;
                                if (tst <= (eps2 * fabsf(D[mm - 1])) * fabsf(D[mm]) + safmin) {
                                    m2 = mm; found = true;
                                }
                            }
                        }
                    }
                    if (m2 < lend) rset(E, m2 - 1, 0.f);
                    float p = rget(D, l - 1);
                    if (m2 == l) {
                        l++;
                        if (l <= lend) continue;
                        break;
                    }
                    if (m2 == l + 1) {
                        float rt1, rt2, cc, ss;
                        laev2f(rget(D, l - 1), rget(E, l - 1), rget(D, l), rt1, rt2, cc, ss);
                        zrot(Z, l - 1, l, cc, ss);
                        rset(D, l - 1, rt1); rset(D, l, rt2); rset(E, l - 1, 0.f);
                        l += 2;
                        if (l <= lend) continue;
                        break;
                    }
                    if (jtot == nmaxit) break;
                    jtot++;
                    float g = fdivf(rget(D, l) - p, 2.f * rget(E, l - 1));
                    float r = lapy2f(g, 1.f);
                    g = rget(D, m2 - 1) - p + fdivf(rget(E, l - 1), g + signf(r, g));
                    float s = 1.f, c = 1.f; p = 0.f;
#pragma unroll
                    for (int i = DDIM - 1; i >= 1; i--) {
                        if (i <= m2 - 1 && i >= l) {
                            float f = s * E[i - 1], b = c * E[i - 1];
                            float rr;
                            lartgf(g, f, c, s, rr);
                            if (i != m2 - 1) E[i] = rr;
                            g = D[i] - p;
                            float r2 = (D[i - 1] - g) * s + 2.f * c * b;
                            p = s * r2;
                            D[i] = g + p;
                            g = c * r2 - b;
                            float t1 = Z[i], t0 = Z[i - 1];
                            Z[i]     = c * t1 + s * t0;
                            Z[i - 1] = -s * t1 + c * t0;
                        }
                    }
                    rset(D, l - 1, rget(D, l - 1) - p);
                    rset(E, l - 1, g);
                }
            } else {
                // ---- QR iteration ----
                while (true) {
                    int m2 = lend;
                    if (l != lend) {
                        bool found = false;
#pragma unroll
                        for (int mm = DDIM; mm >= 2; mm--) {
                            if (!found && mm <= l && mm >= lend + 1) {
                                float tst = fabsf(E[mm - 2]); tst = tst * tst;
                                if (tst <= (eps2 * fabsf(D[mm - 1])) * fabsf(D[mm - 2]) + safmin) {
                                    m2 = mm; found = true;
                                }
                            }
                        }
                    }
                    if (m2 > lend) rset(E, m2 - 2, 0.f);
                    float p = rget(D, l - 1);
                    if (m2 == l) {
                        l--;
                        if (l >= lend) continue;
                        break;
                    }
                    if (m2 == l - 1) {
                        float rt1, rt2, cc, ss;
                        laev2f(rget(D, l - 2), rget(E, l - 2), rget(D, l - 1), rt1, rt2, cc, ss);
                        zrot(Z, l - 2, l - 1, cc, ss);
                        rset(D, l - 2, rt1); rset(D, l - 1, rt2); rset(E, l - 2, 0.f);
                        l -= 2;
                        if (l >= lend) continue;
                        break;
                    }
                    if (jtot == nmaxit) break;
                    jtot++;
                    float g = fdivf(rget(D, l - 2) - p, 2.f * rget(E, l - 2));
                    float r = lapy2f(g, 1.f);
                    g = rget(D, m2 - 1) - p + fdivf(rget(E, l - 2), g + signf(r, g));
                    float s = 1.f, c = 1.f; p = 0.f;
#pragma unroll
                    for (int i = 1; i <= DDIM - 1; i++) {
                        if (i >= m2 && i <= l - 1) {
                            float f = s * E[i - 1], b = c * E[i - 1];
                            float rr;
                            lartgf(g, f, c, s, rr);
                            if (i >= 2 && i != m2) E[i - 2] = rr;
                            g = D[i - 1] - p;
                            float r2 = (D[i] - g) * s + 2.f * c * b;
                            p = s * r2;
                            D[i - 1] = g + p;
                            g = c * r2 - b;
                            float t1 = Z[i], t0 = Z[i - 1];
                            Z[i]     = c * t1 - s * t0;
                            Z[i - 1] = s * t1 + c * t0;
                        }
                    }
                    rset(D, l - 1, rget(D, l - 1) - p);
                    rset(E, l - 2, g);
                }
            }
        }
    }

    // ---- stable ranks replace LAPACK's stable selection sort ----
    // rank[j] = #{k: D[k] < D[j]} + #{k<j: D[k] == D[j]}  (stable ascending)
    int rank[DDIM];
#pragma unroll
    for (int j = 0; j < DDIM; j++) {
        int r = 0;
#pragma unroll
        for (int k = 0; k < DDIM; k++) {
            if (k < j)      r += (D[k] <= D[j]) ? 1 : 0;
            else if (k > j) r += (D[k] <  D[j]) ? 1 : 0;
        }
        rank[j] = r;
    }

    // ---- transpose Z with the permutation folded in: lane c takes the
    //      (unsorted) column whose rank is c ----
    if (lane < n) {
#pragma unroll
        for (int k = 0; k < DDIM; k++) Zs[lane][k] = Z[k];
    }
    __syncwarp();
    int src = 0;
#pragma unroll
    for (int j = 0; j < DDIM; j++) if (rank[j] == lane) src = j;
    float Zc[DDIM];
    if (lane < DDIM) {
#pragma unroll
        for (int r = 0; r < DDIM; r++) Zc[r] = Zs[r][src];   // dynamic LDS ok
    } else {
#pragma unroll
        for (int r = 0; r < DDIM; r++) Zc[r] = 0.f;
    }

    // ---------------- sormtr, column-owned; v via compile-time-lane shfl ---
#pragma unroll
    for (int i = DDIM - 2; i >= 0; i--) {
        float vv[DDIM];
#pragma unroll
        for (int r = i + 2; r < DDIM; r++) vv[r] = __shfl_sync(FULLM, Arow[i], r);
        if (Tau[i] != 0.f) {
            float s = Zc[i + 1];
#pragma unroll
            for (int r = i + 2; r < DDIM; r++) s += vv[r] * Zc[r];
            s *= Tau[i];
            Zc[i + 1] -= s;
#pragma unroll
            for (int r = i + 2; r < DDIM; r++) Zc[r] -= s * vv[r];
        }
    }

    // ---- transpose back (column-owned -> row reads) via smem ----
    __syncwarp();
    if (lane < DDIM) {
#pragma unroll
        for (int r = 0; r < DDIM; r++) Zs[r][lane] = Zc[r];
    }
    __syncwarp();

    // ---------------- MLP: relu(w @ W1^T + b1) @ W2^T + b2; 0.5*(sigmoid+1)
    if (lane < DDIM) {
        float zr[DDIM];
#pragma unroll
        for (int k = 0; k < DDIM; k++) zr[k] = Zs[lane][k];
        float y2 = b2[0];
        for (int h = 0; h < HID; h++) {
            float a = b1[h];
#pragma unroll
            for (int k = 0; k < DDIM; k++) a += zr[k] * W1[h * DDIM + k];
            a = fmaxf(a, 0.f);
            y2 += a * W2[h];
        }
        out[lane] = 0.5f * (fdivf(1.f, 1.f + __expf(-y2)) + 1.f);
    }
}

// ---------------------------------------------------------------------------
extern "C" void kernel_launch(void* const* d_in, const int* in_sizes, int n_in,
                              void* d_out, int out_size) {
    const float* x  = (const float*)d_in[0];
    const float* W1 = (const float*)d_in[1];
    const float* b1 = (const float*)d_in[2];
    const float* W2 = (const float*)d_in[3];
    const float* b2 = (const float*)d_in[4];
    long long nrows = (long long)in_sizes[0] / DDIM;

    gram_kernel<<<GGRID, GTPB>>>(x, nrows);
    solve_kernel<<<SOLVE_GRID, GTPB>>>(W1, b1, W2, b2, (float*)d_out);
}

// round 14
// speedup vs baseline: 1.2681x; 1.0098x over previous
#include <cuda_runtime.h>
#include <cstdint>

#define DDIM 10
#define NPAIR 55
#define GTPB 256
#define GGRID 296            // 148 SMs x 2 blocks -> one full wave
#define ROWS_TILE 512
#define TILE_F4 (ROWS_TILE * DDIM / 4)
#define TILE_FLOATS (ROWS_TILE * DDIM)
#define HID 16
#define FULLM 0xffffffffu
#define SOLVE_GRID 148       // issue-throttle workaround (proven R13)

// Deterministic two-stage reduction scratch (no atomics, no allocation).
__device__ float g_part[NPAIR][GGRID];

// ---------------------------------------------------------------------------
// async-copy helpers
// ---------------------------------------------------------------------------
__device__ __forceinline__ void cp_async16(uint32_t smem_dst, const void* gsrc) {
    asm volatile("cp.async.cg.shared.global [%0], [%1], 16;\n"
                 :: "r"(smem_dst), "l"(gsrc));
}
__device__ __forceinline__ void cp_commit() { asm volatile("cp.async.commit_group;\n"); }
__device__ __forceinline__ void cp_wait0() { asm volatile("cp.async.wait_group 0;\n"); }
__device__ __forceinline__ void cp_wait1() { asm volatile("cp.async.wait_group 1;\n"); }

// ---------------------------------------------------------------------------
// Kernel 1: Gram partials. Proven — unchanged since R6.
// ---------------------------------------------------------------------------
__global__ void __launch_bounds__(GTPB, 2)
gram_kernel(const float* __restrict__ x, long long nrows) {
    __shared__ __align__(16) float sbuf[2][TILE_FLOATS];
    __shared__ float swarp[GTPB / 32][NPAIR];

    float acc[NPAIR];
#pragma unroll
    for (int k = 0; k < NPAIR; k++) acc[k] = 0.f;

    const long long ntiles = (nrows + ROWS_TILE - 1) / ROWS_TILE;
    const long long totalf4 = nrows * (long long)DDIM / 4;
    const float4* xsrc = reinterpret_cast<const float4*>(x);
    const uint32_t sbase = (uint32_t)__cvta_generic_to_shared(&sbuf[0][0]);

    long long t = blockIdx.x;
    bool havecur = (t < ntiles);

    if (havecur) {
        long long base4 = t * (long long)TILE_F4;
#pragma unroll
        for (int j = 0; j < TILE_F4 / GTPB; j++) {
            int i = threadIdx.x + j * GTPB;
            long long g4 = base4 + i;
            if (g4 < totalf4) {
                cp_async16(sbase + (uint32_t)i * 16u, xsrc + g4);
            } else {
                float4 z = make_float4(0.f, 0.f, 0.f, 0.f);
                reinterpret_cast<float4*>(&sbuf[0][0])[i] = z;
            }
        }
        cp_commit();
    }

    int buf = 0;
    while (havecur) {
        long long tn = t + (long long)GGRID;
        bool havenext = (tn < ntiles);
        if (havenext) {
            long long base4 = tn * (long long)TILE_F4;
            uint32_t dbase = sbase + (uint32_t)(buf ^ 1) * (TILE_FLOATS * 4u);
#pragma unroll
            for (int j = 0; j < TILE_F4 / GTPB; j++) {
                int i = threadIdx.x + j * GTPB;
                long long g4 = base4 + i;
                if (g4 < totalf4) {
                    cp_async16(dbase + (uint32_t)i * 16u, xsrc + g4);
                } else {
                    float4 z = make_float4(0.f, 0.f, 0.f, 0.f);
                    reinterpret_cast<float4*>(&sbuf[buf ^ 1][0])[i] = z;
                }
            }
            cp_commit();
            cp_wait1();
        } else {
            cp_wait0();
        }
        __syncthreads();

        const float* sb = &sbuf[buf][0];
#pragma unroll
        for (int half = 0; half < 2; half++) {
            int r0 = threadIdx.x + half * GTPB;
            long long row_g = t * (long long)ROWS_TILE + r0;
            if (row_g < nrows) {
                float r[DDIM];
                const float2* rp = reinterpret_cast<const float2*>(sb + r0 * DDIM);
#pragma unroll
                for (int j = 0; j < 5; j++) {
                    float2 v = rp[j];
                    r[2 * j] = v.x;
                    r[2 * j + 1] = v.y;
                }
                int k = 0;
#pragma unroll
                for (int i = 0; i < DDIM; i++)
#pragma unroll
                    for (int j = i; j < DDIM; j++) acc[k++] += r[i] * r[j];
            }
        }
        __syncthreads();

        t = tn;
        havecur = havenext;
        buf ^= 1;
    }

#pragma unroll
    for (int k = 0; k < NPAIR; k++) {
#pragma unroll
        for (int off = 16; off > 0; off >>= 1)
            acc[k] += __shfl_down_sync(FULLM, acc[k], off);
    }
    int wid = threadIdx.x >> 5, lane = threadIdx.x & 31;
    if (lane == 0) {
#pragma unroll
        for (int k = 0; k < NPAIR; k++) swarp[wid][k] = acc[k];
    }
    __syncthreads();
    if (threadIdx.x < NPAIR) {
        float s = 0.f;
#pragma unroll
        for (int w = 0; w < GTPB / 32; w++) s += swarp[w][threadIdx.x];
        g_part[threadIdx.x][blockIdx.x] = s;
    }
}

// ---------------------------------------------------------------------------
// Fast-approx scalar helpers (sign-safe, R12-proven)
// ---------------------------------------------------------------------------
__device__ __forceinline__ float fdivf(float a, float b) { return __fdividef(a, b); }
__device__ __forceinline__ float fsqrta(float x) {
    float r;
    asm("sqrt.approx.f32 %0, %1;" : "=f"(r) : "f"(x));
    return r;
}
__device__ __forceinline__ float lapy2f(float x, float y) {
    return fsqrta(__fmaf_rn(x, x, y * y));
}
__device__ __forceinline__ float signf(float a, float b) {
    return (b >= 0.f) ? fabsf(a) : -fabsf(a);
}
// LAPACK >= 3.10 slartg convention: c >= 0, r = sign(d, f), sign(s) = sign(g*f).
__device__ __forceinline__ void lartgf(float f, float g, float& c, float& s, float& r) {
    if (g == 0.f) { c = 1.f; s = 0.f; r = f; }
    else if (f == 0.f) { c = 0.f; s = (g > 0.f) ? 1.f : -1.f; r = fabsf(g); }
    else {
        float t = __fmaf_rn(f, f, g * g);
        float rd = rsqrtf(t);
        float d = t * rd;
        c = fabsf(f) * rd;
        r = signf(d, f);
        s = g * copysignf(rd, f);
    }
}
// LAPACK slaev2 — noinline: ONE code copy (I$ footprint), called twice.
__device__ __noinline__ void laev2f(float a, float b, float c_, float& rt1, float& rt2,
                                    float& cs1, float& sn1) {
    float sm = a + c_;
    float df = a - c_;
    float adf = fabsf(df);
    float tb = b + b;
    float ab = fabsf(tb);
    float acmx, acmn;
    if (fabsf(a) > fabsf(c_)) { acmx = a; acmn = c_; } else { acmx = c_; acmn = a; }
    float rt;
    if (adf > ab)      { float q = fdivf(ab, adf); rt = adf * fsqrta(1.f + q * q); }
    else if (adf < ab) { float q = fdivf(adf, ab); rt = ab * fsqrta(1.f + q * q); }
    else               { rt = ab * fsqrta(2.f); }
    int sgn1;
    if (sm < 0.f) {
        rt1 = 0.5f * (sm - rt); sgn1 = -1;
        rt2 = fdivf(acmx, rt1) * acmn - fdivf(b, rt1) * b;
    } else if (sm > 0.f) {
        rt1 = 0.5f * (sm + rt); sgn1 = 1;
        rt2 = fdivf(acmx, rt1) * acmn - fdivf(b, rt1) * b;
    } else {
        rt1 = 0.5f * rt; rt2 = -0.5f * rt; sgn1 = 1;
    }
    float cs; int sgn2;
    if (df >= 0.f) { cs = df + rt; sgn2 = 1; }
    else           { cs = df - rt; sgn2 = -1; }
    float acs = fabsf(cs);
    if (acs > ab) {
        float ct = -fdivf(tb, cs);
        sn1 = rsqrtf(1.f + ct * ct);
        cs1 = ct * sn1;
    } else {
        if (ab == 0.f) { cs1 = 1.f; sn1 = 0.f; }
        else {
            float tn = -fdivf(cs, tb);
            cs1 = rsqrtf(1.f + tn * tn);
            sn1 = tn * cs1;
        }
    }
    if (sgn1 == sgn2) { float tn = cs1; cs1 = -sn1; sn1 = tn; }
}

// ---------------------------------------------------------------------------
// Kernel 2. R14 delta: steqr rebuilt as COMPACT dynamic loops (small I$
// footprint) with D/E in smem (uniform scalar chain; all lanes write same
// values — R6-validated) and Z row-owned in smem with rotations fused inline
// (R8-validated order). ssytd2 (R11 shfl), rank-permutation sort (R13),
// sormtr (R11), grid=148 ballast (R13) all kept.
// ---------------------------------------------------------------------------
__global__ void solve_kernel(const float* __restrict__ W1, const float* __restrict__ b1,
                             const float* __restrict__ W2, const float* __restrict__ b2,
                             float* __restrict__ out) {
    if (blockIdx.x != 0) return;        // throttle-bypass ballast blocks

    __shared__ float gram[NPAIR];
    __shared__ float Zs[DDIM][DDIM];
    __shared__ float dd[DDIM], ee[DDIM];

    const int tid = threadIdx.x;
    const int wrp = tid >> 5;
    const int lane = tid & 31;
    const int n = DDIM;

    // ---- stage 1: tree-reduce partials (all 8 warps) ----
    for (int k = wrp; k < NPAIR; k += 8) {
        float s = 0.f;
        for (int i = lane; i < GGRID; i += 32) s += g_part[k][i];
#pragma unroll
        for (int off = 16; off > 0; off >>= 1)
            s += __shfl_down_sync(FULLM, s, off);
        if (lane == 0) gram[k] = s;
    }
    __syncthreads();
    if (tid >= 32) return;

    // ---- lane r (<10) owns row r of symmetric A in registers ----
    float Arow[DDIM];
    if (lane < DDIM) {
#pragma unroll
        for (int c = 0; c < DDIM; c++) {
            int lo = (lane < c) ? lane : c;
            int hi = (lane < c) ? c : lane;
            Arow[c] = gram[lo * DDIM - (lo * (lo - 1)) / 2 + (hi - lo)];
        }
    } else {
#pragma unroll
        for (int c = 0; c < DDIM; c++) Arow[c] = 0.f;
    }

    float Tau[DDIM - 1];

    // ---------------- ssytd2 (uplo='L'), lane-owns-row (R11) ----------------
#pragma unroll
    for (int i = 0; i < DDIM - 1; i++) {
        float vbc[DDIM];
#pragma unroll
        for (int c = i + 1; c < DDIM; c++) vbc[c] = __shfl_sync(FULLM, Arow[i], c);
        float alpha = vbc[i + 1];
        float xnorm = 0.f;
#pragma unroll
        for (int r = i + 2; r < DDIM; r++) xnorm += vbc[r] * vbc[r];
        xnorm = fsqrta(xnorm);
        float taui = 0.f, Ei;
        if (xnorm != 0.f) {
            float beta = -signf(lapy2f(alpha, xnorm), alpha);
            taui = fdivf(beta - alpha, beta);
            float sc = fdivf(1.f, alpha - beta);
#pragma unroll
            for (int r = i + 2; r < DDIM; r++) vbc[r] *= sc;
            if (lane >= i + 2 && lane < DDIM) Arow[i] *= sc;   // persist v for sormtr
            Ei = beta;
        } else {
            Ei = alpha;
        }
        ee[i] = Ei;                         // uniform value, benign multi-write
        Tau[i] = taui;
        if (taui != 0.f) {
            float s = Arow[i + 1];
#pragma unroll
            for (int c = i + 2; c < DDIM; c++) s += Arow[c] * vbc[c];
            float pvr = taui * s;
            float pvb[DDIM];
#pragma unroll
            for (int r = i + 1; r < DDIM; r++) pvb[r] = __shfl_sync(FULLM, pvr, r);
            float vtp = pvb[i + 1];
#pragma unroll
            for (int r = i + 2; r < DDIM; r++) vtp += pvb[r] * vbc[r];
            float alph = -0.5f * taui * vtp;
            pvb[i + 1] += alph;
#pragma unroll
            for (int r = i + 2; r < DDIM; r++) pvb[r] += alph * vbc[r];
            if (lane >= i + 1 && lane < DDIM) {
                float vr = (lane == i + 1) ? 1.f : Arow[i];
                float wr = (lane == i + 1) ? (pvr + alph) : (pvr + alph * Arow[i]);
#pragma unroll
                for (int c = i + 1; c < DDIM; c++) {
                    float vc = (c == i + 1) ? 1.f : vbc[c];
                    Arow[c] -= vr * pvb[c] + wr * vc;
                }
            }
        }
        dd[i] = __shfl_sync(FULLM, Arow[i], i);
    }
    dd[DDIM - 1] = __shfl_sync(FULLM, Arow[DDIM - 1], DDIM - 1);
    ee[DDIM - 1] = 0.f;

    // Z = I, row-owned in smem
    if (lane < DDIM) {
#pragma unroll
        for (int c = 0; c < DDIM; c++) Zs[lane][c] = (lane == c) ? 1.f : 0.f;
    }
    __syncwarp();

    // ---------------- ssteqr (compz='I'), COMPACT dynamic form --------------
    // All lanes run the identical scalar chain on smem dd/ee (uniform data ->
    // uniform control); multi-lane same-value smem writes are benign (R6).
    // Z rotations applied inline in generation order (R8); lane owns row.
    {
        const float eps = 5.9604645e-8f;
        const float eps2 = eps * eps;
        const float safmin = 1.17549435e-38f;
        const int nmaxit = n * 30;
        int jtot = 0;
        int l1 = 1;
#define Dv(i) dd[(i) - 1]
#define Ev(i) ee[(i) - 1]
        while (l1 <= n) {
            if (l1 > 1) Ev(l1 - 1) = 0.f;
            int m = n;
            for (int mm = l1; mm <= n - 1; mm++) {
                float tst = fabsf(Ev(mm));
                if (tst == 0.f) { m = mm; break; }
                if (tst <= fsqrta(fabsf(Dv(mm))) * fsqrta(fabsf(Dv(mm + 1))) * eps) {
                    Ev(mm) = 0.f; m = mm; break;
                }
            }
            int l = l1, lend = m;
            l1 = m + 1;
            if (lend == l) continue;
            float anorm = 0.f;
            for (int i = l; i <= lend; i++) anorm = fmaxf(anorm, fabsf(Dv(i)));
            for (int i = l; i <= lend - 1; i++) anorm = fmaxf(anorm, fabsf(Ev(i)));
            if (anorm == 0.f) continue;
            if (fabsf(Dv(lend)) < fabsf(Dv(l))) { int t = l; l = lend; lend = t; }

            if (lend > l) {
                // ---- QL ----
                while (true) {
                    int m2 = lend;
                    if (l != lend) {
                        for (int mm = l; mm <= lend - 1; mm++) {
                            float tst = Ev(mm) * Ev(mm);
                            if (tst <= (eps2 * fabsf(Dv(mm))) * fabsf(Dv(mm + 1)) + safmin) {
                                m2 = mm; break;
                            }
                        }
                    }
                    if (m2 < lend) Ev(m2) = 0.f;
                    float p = Dv(l);
                    if (m2 == l) {
                        l++;
                        if (l <= lend) continue;
                        break;
                    }
                    if (m2 == l + 1) {
                        float rt1, rt2, cc, ss;
                        laev2f(Dv(l), Ev(l), Dv(l + 1), rt1, rt2, cc, ss);
                        if (lane < DDIM) {
                            float t1 = Zs[lane][l], t0 = Zs[lane][l - 1];
                            Zs[lane][l] = cc * t1 - ss * t0;
                            Zs[lane][l - 1] = ss * t1 + cc * t0;
                        }
                        Dv(l) = rt1; Dv(l + 1) = rt2; Ev(l) = 0.f;
                        l += 2;
                        if (l <= lend) continue;
                        break;
                    }
                    if (jtot == nmaxit) break;
                    jtot++;
                    float g = fdivf(Dv(l + 1) - p, 2.f * Ev(l));
                    float r = lapy2f(g, 1.f);
                    g = Dv(m2) - p + fdivf(Ev(l), g + signf(r, g));
                    float s = 1.f, c = 1.f; p = 0.f;
                    for (int i = m2 - 1; i >= l; i--) {
                        float Ei = Ev(i);
                        float f = s * Ei, b = c * Ei;
                        float rr;
                        lartgf(g, f, c, s, rr);
                        if (i != m2 - 1) Ev(i + 1) = rr;
                        float g2 = Dv(i + 1) - p;
                        float r2 = (Dv(i) - g2) * s + 2.f * c * b;
                        p = s * r2;
                        Dv(i + 1) = g2 + p;
                        g = c * r2 - b;
                        if (lane < DDIM) {          // ct=c, st=-s on cols (i-1, i)
                            float t1 = Zs[lane][i], t0 = Zs[lane][i - 1];
                            Zs[lane][i] = c * t1 + s * t0;
                            Zs[lane][i - 1] = -s * t1 + c * t0;
                        }
                    }
                    Dv(l) -= p;
                    Ev(l) = g;
                }
            } else {
                // ---- QR ----
                while (true) {
                    int m2 = lend;
                    if (l != lend) {
                        for (int mm = l; mm >= lend + 1; mm--) {
                            float tst = Ev(mm - 1) * Ev(mm - 1);
                            if (tst <= (eps2 * fabsf(Dv(mm))) * fabsf(Dv(mm - 1)) + safmin) {
                                m2 = mm; break;
                            }
                        }
                    }
                    if (m2 > lend) Ev(m2 - 1) = 0.f;
                    float p = Dv(l);
                    if (m2 == l) {
                        l--;
                        if (l >= lend) continue;
                        break;
                    }
                    if (m2 == l - 1) {
                        float rt1, rt2, cc, ss;
                        laev2f(Dv(l - 1), Ev(l - 1), Dv(l), rt1, rt2, cc, ss);
                        if (lane < DDIM) {
                            float t1 = Zs[lane][l - 1], t0 = Zs[lane][l - 2];
                            Zs[lane][l - 1] = cc * t1 - ss * t0;
                            Zs[lane][l - 2] = ss * t1 + cc * t0;
                        }
                        Dv(l - 1) = rt1; Dv(l) = rt2; Ev(l - 1) = 0.f;
                        l -= 2;
                        if (l >= lend) continue;
                        break;
                    }
                    if (jtot == nmaxit) break;
                    jtot++;
                    float g = fdivf(Dv(l - 1) - p, 2.f * Ev(l - 1));
                    float r = lapy2f(g, 1.f);
                    g = Dv(m2) - p + fdivf(Ev(l - 1), g + signf(r, g));
                    float s = 1.f, c = 1.f; p = 0.f;
                    for (int i = m2; i <= l - 1; i++) {
                        float Ei = Ev(i);
                        float f = s * Ei, b = c * Ei;
                        float rr;
                        lartgf(g, f, c, s, rr);
                        if (i != m2) Ev(i - 1) = rr;
                        float g2 = Dv(i) - p;
                        float r2 = (Dv(i + 1) - g2) * s + 2.f * c * b;
                        p = s * r2;
                        Dv(i) = g2 + p;
                        g = c * r2 - b;
                        if (lane < DDIM) {          // ct=c, st=s on cols (i-1, i)
                            float t1 = Zs[lane][i], t0 = Zs[lane][i - 1];
                            Zs[lane][i] = c * t1 - s * t0;
                            Zs[lane][i - 1] = s * t1 + c * t0;
                        }
                    }
                    Dv(l) -= p;
                    Ev(l - 1) = g;
                }
            }
        }
#undef Dv
#undef Ev
    }
    __syncwarp();

    // ---- stable ranks replace the stable selection sort (R13) ----
    // rank[j] = #{k: dd[k] < dd[j]} + #{k<j: dd[k] == dd[j]}
    int src = 0;
    if (lane < DDIM) {
        for (int j = 0; j < DDIM; j++) {
            float dj = dd[j];
            int r = 0;
            for (int k = 0; k < DDIM; k++) {
                if (k < j)      r += (dd[k] <= dj) ? 1 : 0;
                else if (k > j) r += (dd[k] <  dj) ? 1 : 0;
            }
            if (r == lane) src = j;
        }
    }

    // ---- gather permuted columns: lane c takes unsorted column of rank c --
    float Zc[DDIM];
    if (lane < DDIM) {
#pragma unroll
        for (int r = 0; r < DDIM; r++) Zc[r] = Zs[r][src];
    } else {
#pragma unroll
        for (int r = 0; r < DDIM; r++) Zc[r] = 0.f;
    }
    __syncwarp();

    // ---------------- sormtr, column-owned; v via compile-time-lane shfl ---
#pragma unroll
    for (int i = DDIM - 2; i >= 0; i--) {
        float vv[DDIM];
#pragma unroll
        for (int r = i + 2; r < DDIM; r++) vv[r] = __shfl_sync(FULLM, Arow[i], r);
        if (Tau[i] != 0.f) {
            float s = Zc[i + 1];
#pragma unroll
            for (int r = i + 2; r < DDIM; r++) s += vv[r] * Zc[r];
            s *= Tau[i];
            Zc[i + 1] -= s;
#pragma unroll
            for (int r = i + 2; r < DDIM; r++) Zc[r] -= s * vv[r];
        }
    }

    // ---- transpose back (column-owned -> row reads) via smem ----
    if (lane < DDIM) {
#pragma unroll
        for (int r = 0; r < DDIM; r++) Zs[r][lane] = Zc[r];
    }
    __syncwarp();

    // ---------------- MLP: relu(w @ W1^T + b1) @ W2^T + b2; 0.5*(sigmoid+1)
    if (lane < DDIM) {
        float zr[DDIM];
#pragma unroll
        for (int k = 0; k < DDIM; k++) zr[k] = Zs[lane][k];
        float y2 = b2[0];
        for (int h = 0; h < HID; h++) {
            float a = b1[h];
#pragma unroll
            for (int k = 0; k < DDIM; k++) a += zr[k] * W1[h * DDIM + k];
            a = fmaxf(a, 0.f);
            y2 += a * W2[h];
        }
        out[lane] = 0.5f * (fdivf(1.f, 1.f + __expf(-y2)) + 1.f);
    }
}

// ---------------------------------------------------------------------------
extern "C" void kernel_launch(void* const* d_in, const int* in_sizes, int n_in,
                              void* d_out, int out_size) {
    const float* x  = (const float*)d_in[0];
    const float* W1 = (const float*)d_in[1];
    const float* b1 = (const float*)d_in[2];
    const float* W2 = (const float*)d_in[3];
    const float* b2 = (const float*)d_in[4];
    long long nrows = (long long)in_sizes[0] / DDIM;

    gram_kernel<<<GGRID, GTPB>>>(x, nrows);
    solve_kernel<<<SOLVE_GRID, GTPB>>>(W1, b1, W2, b2, (float*)d_out);
}